// round 13
// baseline (speedup 1.0000x reference)
#include <cuda_runtime.h>
#include <math.h>
#include <float.h>

typedef long long ll;

#define Bb 2
#define Tt 2048
#define BT 4096
#define Dd 1024
#define Hh 16
#define HS 64
#define Ff 4096
#define Vv 32000
#define Ll 8

// ---------------- static scratch (no allocations allowed) ----------------
__device__ float g_x [BT*Dd];
__device__ float g_h [BT*Dd];
__device__ float g_q [BT*Dd];
__device__ float g_k [BT*Dd];
__device__ float g_v [BT*Dd];
__device__ float g_vs[BT*Dd];
__device__ float g_o [BT*Dd];
__device__ float g_p [BT*Dd];
__device__ float g_f [BT*Ff];
__device__ float g_att[134217728];     // B*H*T*T = 512MB
__device__ float g_ci [Bb*Hh*Tt];
__device__ float g_wq [Dd*Dd];
__device__ float g_wk [Dd*Dd];
__device__ float g_wv [Dd*Dd];
__device__ float g_rl [BT];
__device__ float g_loss[4];

// ---------------- reductions ----------------
__device__ __forceinline__ float blockReduceSum(float v){
    __shared__ float sh[33];
    int lane = threadIdx.x & 31, wid = threadIdx.x >> 5;
    #pragma unroll
    for (int o = 16; o; o >>= 1) v += __shfl_xor_sync(0xffffffffu, v, o);
    __syncthreads();
    if (lane == 0) sh[wid] = v;
    __syncthreads();
    if (wid == 0) {
        int nw = (blockDim.x + 31) >> 5;
        float r = (lane < nw) ? sh[lane] : 0.f;
        #pragma unroll
        for (int o = 16; o; o >>= 1) r += __shfl_xor_sync(0xffffffffu, r, o);
        if (lane == 0) sh[32] = r;
    }
    __syncthreads();
    return sh[32];
}

__device__ __forceinline__ float blockReduceMax(float v){
    __shared__ float shm[33];
    int lane = threadIdx.x & 31, wid = threadIdx.x >> 5;
    #pragma unroll
    for (int o = 16; o; o >>= 1) v = fmaxf(v, __shfl_xor_sync(0xffffffffu, v, o));
    __syncthreads();
    if (lane == 0) shm[wid] = v;
    __syncthreads();
    if (wid == 0) {
        int nw = (blockDim.x + 31) >> 5;
        float r = (lane < nw) ? shm[lane] : -FLT_MAX;
        #pragma unroll
        for (int o = 16; o; o >>= 1) r = fmaxf(r, __shfl_xor_sync(0xffffffffu, r, o));
        if (lane == 0) shm[32] = r;
    }
    __syncthreads();
    return shm[32];
}

// ---------------- generic SGEMM (NN) with fused epilogue ----------------
// C[M,N] = A[M,K] * B[K,N]; EPI: 0=none, 1=+bias, 2=relu(+bias)
// batch offset: bz -> zo=bz/zdiv, zi=bz%zdiv ; base += zo*sXo + zi*sXi
// tri!=0: K truncated to bm+BM (causal lower-triangular A)
template<int BM,int BN,int BK,int TM,int TN,int EPI>
__global__ void __launch_bounds__((BM/TM)*(BN/TN))
sgemm_nn(int M,int N,int K,
         const float* __restrict__ A,int lda,
         const float* __restrict__ B,int ldb,
         float* __restrict__ C,int ldc,
         const float* __restrict__ bias,
         int zdiv, ll sAo, ll sAi, ll sBo, ll sBi, ll sCo, ll sCi, int tri)
{
    constexpr int THREADS = (BM/TM)*(BN/TN);
    __shared__ __align__(16) float As[BK][BM];
    __shared__ __align__(16) float Bs[BK][BN];

    int bz = blockIdx.z;
    int zo = bz / zdiv, zi = bz % zdiv;
    A += (ll)zo*sAo + (ll)zi*sAi;
    B += (ll)zo*sBo + (ll)zi*sBi;
    C += (ll)zo*sCo + (ll)zi*sCi;

    int bm = blockIdx.y * BM, bn = blockIdx.x * BN;
    int Keff = tri ? min(K, bm + BM) : K;

    int tid = threadIdx.x;
    int tx = tid % (BN/TN), ty = tid / (BN/TN);

    constexpr int LA = (BM*BK)/(4*THREADS);
    constexpr int LB = (BK*BN)/(4*THREADS);
    constexpr int A_RPP = THREADS/(BK/4);
    constexpr int B_RPP = THREADS/(BN/4);
    int a_c4 = tid % (BK/4), a_r = tid / (BK/4);
    int b_c4 = tid % (BN/4), b_r = tid / (BN/4);

    float acc[TM][TN] = {};

    for (int k0 = 0; k0 < Keff; k0 += BK) {
        #pragma unroll
        for (int p = 0; p < LA; p++) {
            int r = a_r + p * A_RPP;
            float4 v = *(const float4*)&A[(ll)(bm + r)*lda + k0 + a_c4*4];
            As[a_c4*4+0][r] = v.x; As[a_c4*4+1][r] = v.y;
            As[a_c4*4+2][r] = v.z; As[a_c4*4+3][r] = v.w;
        }
        #pragma unroll
        for (int p = 0; p < LB; p++) {
            int r = b_r + p * B_RPP;
            *(float4*)&Bs[r][b_c4*4] = *(const float4*)&B[(ll)(k0 + r)*ldb + bn + b_c4*4];
        }
        __syncthreads();
        #pragma unroll
        for (int kk = 0; kk < BK; kk++) {
            float a[TM], b[TN];
            #pragma unroll
            for (int i = 0; i < TM; i += 4)
                *(float4*)&a[i] = *(const float4*)&As[kk][ty*TM + i];
            #pragma unroll
            for (int j = 0; j < TN; j += 4)
                *(float4*)&b[j] = *(const float4*)&Bs[kk][tx*TN + j];
            #pragma unroll
            for (int i = 0; i < TM; i++)
                #pragma unroll
                for (int j = 0; j < TN; j++)
                    acc[i][j] = fmaf(a[i], b[j], acc[i][j]);
        }
        __syncthreads();
    }

    #pragma unroll
    for (int i = 0; i < TM; i++) {
        int row = bm + ty*TM + i;
        float* crow = C + (ll)row*ldc + bn + tx*TN;
        #pragma unroll
        for (int j0 = 0; j0 < TN; j0 += 4) {
            float4 v;
            v.x = acc[i][j0+0]; v.y = acc[i][j0+1];
            v.z = acc[i][j0+2]; v.w = acc[i][j0+3];
            if (EPI >= 1) {
                float4 bv = *(const float4*)&bias[bn + tx*TN + j0];
                v.x += bv.x; v.y += bv.y; v.z += bv.z; v.w += bv.w;
            }
            if (EPI == 2) {
                v.x = fmaxf(v.x, 0.f); v.y = fmaxf(v.y, 0.f);
                v.z = fmaxf(v.z, 0.f); v.w = fmaxf(v.w, 0.f);
            }
            *(float4*)&crow[j0] = v;
        }
    }
}

// ---------------- attention: E = exp(scale * Q K^T) masked (NT GEMM) ----------------
// grid (T/128, T/128, B*H), 256 threads
__global__ void __launch_bounds__(256)
attn_scores_kernel(const float* __restrict__ Q, const float* __restrict__ Km,
                   float* __restrict__ E)
{
    int bz = blockIdx.z;
    int b = bz >> 4, h = bz & 15;
    const float* Qb = Q + (ll)b*Tt*Dd + h*HS;
    const float* Kb = Km + (ll)b*Tt*Dd + h*HS;
    float* Eb = E + (ll)bz*Tt*Tt;

    int bm = blockIdx.y * 128, bn = blockIdx.x * 128;
    int tid = threadIdx.x;

    if (bn > bm + 127) {  // entire tile above diagonal -> zeros
        for (int i = tid; i < 128*32; i += 256) {
            int r = i >> 5, c4 = i & 31;
            *(float4*)&Eb[(ll)(bm + r)*Tt + bn + c4*4] = make_float4(0.f,0.f,0.f,0.f);
        }
        return;
    }

    __shared__ __align__(16) float As[16][128];
    __shared__ __align__(16) float Bs[16][128];
    int tx = tid & 15, ty = tid >> 4;
    int c4 = tid & 3, rr = tid >> 2;   // 64 rows per pass, 4 cols(f4)
    float acc[8][8] = {};

    for (int k0 = 0; k0 < HS; k0 += 16) {
        #pragma unroll
        for (int p = 0; p < 2; p++) {
            int r = rr + p*64;
            float4 v = *(const float4*)&Qb[(ll)(bm + r)*Dd + k0 + c4*4];
            As[c4*4+0][r] = v.x; As[c4*4+1][r] = v.y; As[c4*4+2][r] = v.z; As[c4*4+3][r] = v.w;
            float4 w = *(const float4*)&Kb[(ll)(bn + r)*Dd + k0 + c4*4];
            Bs[c4*4+0][r] = w.x; Bs[c4*4+1][r] = w.y; Bs[c4*4+2][r] = w.z; Bs[c4*4+3][r] = w.w;
        }
        __syncthreads();
        #pragma unroll
        for (int kk = 0; kk < 16; kk++) {
            float a[8], b2[8];
            #pragma unroll
            for (int i = 0; i < 8; i += 4) *(float4*)&a[i]  = *(const float4*)&As[kk][ty*8 + i];
            #pragma unroll
            for (int j = 0; j < 8; j += 4) *(float4*)&b2[j] = *(const float4*)&Bs[kk][tx*8 + j];
            #pragma unroll
            for (int i = 0; i < 8; i++)
                #pragma unroll
                for (int j = 0; j < 8; j++)
                    acc[i][j] = fmaf(a[i], b2[j], acc[i][j]);
        }
        __syncthreads();
    }

    const float scale = 0.03125f;   // D^-0.5 = 1/32
    #pragma unroll
    for (int i = 0; i < 8; i++) {
        int row = bm + ty*8 + i;
        #pragma unroll
        for (int j0 = 0; j0 < 8; j0 += 4) {
            float4 v;
            int col = bn + tx*8 + j0;
            v.x = (col+0 <= row) ? __expf(scale*acc[i][j0+0]) : 0.f;
            v.y = (col+1 <= row) ? __expf(scale*acc[i][j0+1]) : 0.f;
            v.z = (col+2 <= row) ? __expf(scale*acc[i][j0+2]) : 0.f;
            v.w = (col+3 <= row) ? __expf(scale*acc[i][j0+3]) : 0.f;
            *(float4*)&Eb[(ll)row*Tt + col] = v;
        }
    }
}

// ---------------- column-sum inverse over query axis ----------------
__global__ void colinv_kernel(const float* __restrict__ E, float* __restrict__ ci)
{
    int bz = blockIdx.y;
    int s = blockIdx.x * 256 + threadIdx.x;
    const float* Eb = E + (ll)bz*Tt*Tt;
    int t0 = blockIdx.x * 256;  // rows below block start are all zero
    float sum = 0.f;
    for (int t = t0; t < Tt; t++) sum += Eb[(ll)t*Tt + s];
    ci[bz*Tt + s] = 1.f / sum;
}

// ---------------- v' = v / colsum ----------------
__global__ void vscale_kernel(const float* __restrict__ v2, const float* __restrict__ ci,
                              float* __restrict__ vs)
{
    ll i4 = (ll)blockIdx.x * 256 + threadIdx.x;
    ll i = i4 * 4;
    int bt = (int)(i >> 10);
    int d  = (int)(i & 1023);
    int h = d >> 6;
    int b = bt >> 11, t = bt & 2047;
    float c = ci[((b*Hh + h) << 11) + t];
    float4 v = ((const float4*)v2)[i4];
    v.x *= c; v.y *= c; v.z *= c; v.w *= c;
    ((float4*)vs)[i4] = v;
}

// ---------------- layernorm (one block per row, D=1024, 256 threads) ----------------
__global__ void ln_kernel(const float* __restrict__ x, const float* __restrict__ g,
                          const float* __restrict__ bta, float* __restrict__ y)
{
    int row = blockIdx.x, tid = threadIdx.x;
    float4 v = ((const float4*)(x + (ll)row*Dd))[tid];
    float mean = blockReduceSum(v.x + v.y + v.z + v.w) * (1.f/1024.f);
    float dx = v.x - mean, dy = v.y - mean, dz = v.z - mean, dw = v.w - mean;
    float var = blockReduceSum(dx*dx + dy*dy + dz*dz + dw*dw) * (1.f/1024.f);
    float rstd = rsqrtf(var + 1e-5f);
    float4 gv = ((const float4*)g)[tid];
    float4 bv = ((const float4*)bta)[tid];
    float4 o;
    o.x = dx*rstd*gv.x + bv.x; o.y = dy*rstd*gv.y + bv.y;
    o.z = dz*rstd*gv.z + bv.z; o.w = dw*rstd*gv.w + bv.w;
    ((float4*)(y + (ll)row*Dd))[tid] = o;
}

// ---------------- embedding ----------------
__global__ void embed_kernel(const int* __restrict__ idx, const float* __restrict__ tok,
                             const float* __restrict__ pos, float* __restrict__ x)
{
    int bt = blockIdx.x, tid = threadIdx.x;
    int t = bt & (Tt - 1);
    int token = idx[bt];
    float4 a = ((const float4*)(tok + (ll)token*Dd))[tid];
    float4 p = ((const float4*)(pos + (ll)t*Dd))[tid];
    float4 o = make_float4(a.x+p.x, a.y+p.y, a.z+p.z, a.w+p.w);
    ((float4*)(x + (ll)bt*Dd))[tid] = o;
}

// ---------------- elementwise add ----------------
__global__ void add_kernel(const float* __restrict__ a, const float* __restrict__ b,
                           float* __restrict__ c)
{
    ll i = (ll)blockIdx.x * 256 + threadIdx.x;
    float4 av = ((const float4*)a)[i];
    float4 bv = ((const float4*)b)[i];
    ((float4*)c)[i] = make_float4(av.x+bv.x, av.y+bv.y, av.z+bv.z, av.w+bv.w);
}

// ---------------- pack [H,D,hs] -> [D, H*hs] for q/k/v ----------------
__global__ void pack_qkv_kernel(const float* __restrict__ wq, const float* __restrict__ wk,
                                const float* __restrict__ wv,
                                float* __restrict__ pq, float* __restrict__ pk,
                                float* __restrict__ pv)
{
    int n = blockIdx.x * 256 + threadIdx.x;  // over D*D
    int d = n >> 10, c = n & 1023;
    int h = c >> 6, e = c & 63;
    ll src = ((ll)h*Dd + d)*64 + e;
    pq[n] = wq[src]; pk[n] = wk[src]; pv[n] = wv[src];
}

// ---------------- per-row cross-entropy ----------------
__global__ void rowloss_kernel(const float* __restrict__ logits, const int* __restrict__ tg,
                               float* __restrict__ rl)
{
    int row = blockIdx.x, tid = threadIdx.x;
    const float* lr = logits + (ll)row * Vv;
    float mx = -FLT_MAX;
    for (int i = tid; i < Vv; i += 256) mx = fmaxf(mx, lr[i]);
    mx = blockReduceMax(mx);
    float se = 0.f;
    for (int i = tid; i < Vv; i += 256) se += __expf(lr[i] - mx);
    se = blockReduceSum(se);
    if (tid == 0) rl[row] = mx + logf(se) - lr[tg[row]];
}

__global__ void lossreduce_kernel(const float* __restrict__ rl, float* __restrict__ out)
{
    float s = 0.f;
    for (int i = threadIdx.x; i < BT; i += 256) s += rl[i];
    s = blockReduceSum(s);
    if (threadIdx.x == 0) out[0] = s * (1.f / (float)BT);
}

// ---------------- host-side GEMM dispatch ----------------
static void gemm_main(int M, int N, int K, const float* A, int lda,
                      const float* B, int ldb, float* C, int ldc,
                      const float* bias, int epi)
{
    dim3 grid(N/128, M/128, 1);
    if (epi == 0)
        sgemm_nn<128,128,16,8,8,0><<<grid,256>>>(M,N,K,A,lda,B,ldb,C,ldc,bias,1,0,0,0,0,0,0,0);
    else if (epi == 1)
        sgemm_nn<128,128,16,8,8,1><<<grid,256>>>(M,N,K,A,lda,B,ldb,C,ldc,bias,1,0,0,0,0,0,0,0);
    else
        sgemm_nn<128,128,16,8,8,2><<<grid,256>>>(M,N,K,A,lda,B,ldb,C,ldc,bias,1,0,0,0,0,0,0,0);
}

extern "C" void kernel_launch(void* const* d_in, const int* in_sizes, int n_in,
                              void* d_out, int out_size)
{
    const int*   idx   = (const int*)  d_in[0];
    const int*   tgt   = (const int*)  d_in[1];
    const float* tok   = (const float*)d_in[2];
    const float* pos   = (const float*)d_in[3];
    const float* wq    = (const float*)d_in[4];
    const float* wk    = (const float*)d_in[5];
    const float* wv    = (const float*)d_in[6];
    const float* wproj = (const float*)d_in[7];
    const float* bproj = (const float*)d_in[8];
    const float* ln1g  = (const float*)d_in[9];
    const float* ln1b  = (const float*)d_in[10];
    const float* ln2g  = (const float*)d_in[11];
    const float* ln2b  = (const float*)d_in[12];
    const float* w1    = (const float*)d_in[13];
    const float* b1    = (const float*)d_in[14];
    const float* w2    = (const float*)d_in[15];
    const float* b2    = (const float*)d_in[16];
    const float* lnfg  = (const float*)d_in[17];
    const float* lnfb  = (const float*)d_in[18];
    const float* wlm   = (const float*)d_in[19];
    const float* blm   = (const float*)d_in[20];

    float *px,*ph,*pq,*pk,*pv,*pvs,*po,*pp,*pf,*pe,*pci,*pwq,*pwk,*pwv,*prl,*plo;
    cudaGetSymbolAddress((void**)&px,  g_x);
    cudaGetSymbolAddress((void**)&ph,  g_h);
    cudaGetSymbolAddress((void**)&pq,  g_q);
    cudaGetSymbolAddress((void**)&pk,  g_k);
    cudaGetSymbolAddress((void**)&pv,  g_v);
    cudaGetSymbolAddress((void**)&pvs, g_vs);
    cudaGetSymbolAddress((void**)&po,  g_o);
    cudaGetSymbolAddress((void**)&pp,  g_p);
    cudaGetSymbolAddress((void**)&pf,  g_f);
    cudaGetSymbolAddress((void**)&pe,  g_att);
    cudaGetSymbolAddress((void**)&pci, g_ci);
    cudaGetSymbolAddress((void**)&pwq, g_wq);
    cudaGetSymbolAddress((void**)&pwk, g_wk);
    cudaGetSymbolAddress((void**)&pwv, g_wv);
    cudaGetSymbolAddress((void**)&prl, g_rl);
    cudaGetSymbolAddress((void**)&plo, g_loss);

    float* out = (float*)d_out;
    const ll NL = (ll)BT * Vv;               // 131,072,000
    float* logits = (out_size >= (int)NL) ? out : pe;   // reuse E scratch if needed
    float* lossp  = plo;
    if ((ll)out_size == NL + 1) lossp = out + NL;
    else if (out_size == 1)     lossp = out;

    embed_kernel<<<BT, 256>>>(idx, tok, pos, px);

    for (int l = 0; l < Ll; l++) {
        ln_kernel<<<BT, 256>>>(px, ln1g + (ll)l*Dd, ln1b + (ll)l*Dd, ph);

        pack_qkv_kernel<<<(Dd*Dd)/256, 256>>>(
            wq + (ll)l*Hh*Dd*HS, wk + (ll)l*Hh*Dd*HS, wv + (ll)l*Hh*Dd*HS,
            pwq, pwk, pwv);

        gemm_main(BT, Dd, Dd, ph, Dd, pwq, Dd, pq, Dd, nullptr, 0);
        gemm_main(BT, Dd, Dd, ph, Dd, pwk, Dd, pk, Dd, nullptr, 0);
        gemm_main(BT, Dd, Dd, ph, Dd, pwv, Dd, pv, Dd, nullptr, 0);

        attn_scores_kernel<<<dim3(Tt/128, Tt/128, Bb*Hh), 256>>>(pq, pk, pe);
        colinv_kernel<<<dim3(Tt/256, Bb*Hh), 256>>>(pe, pci);
        vscale_kernel<<<(BT*Dd)/1024, 256>>>(pv, pci, pvs);

        // O = E @ V'   batched over (b,h): M=T, N=64, K=T, causal K truncation
        {
            dim3 grid(1, Tt/128, Bb*Hh);
            sgemm_nn<128,64,16,8,8,0><<<grid,128>>>(
                Tt, 64, Tt,
                pe, Tt,
                pvs, Dd,
                po, Dd,
                nullptr,
                Hh,
                (ll)Hh*Tt*Tt, (ll)Tt*Tt,   // A: bz*T*T
                (ll)Tt*Dd, 64LL,           // B: b*T*D + h*64
                (ll)Tt*Dd, 64LL,           // C: b*T*D + h*64
                1);
        }

        gemm_main(BT, Dd, Dd, po, Dd, wproj + (ll)l*Dd*Dd, Dd, pp, Dd,
                  bproj + (ll)l*Dd, 1);
        add_kernel<<<(BT*Dd)/1024, 256>>>(ph, pp, px);           // x = h + o

        ln_kernel<<<BT, 256>>>(px, ln2g + (ll)l*Dd, ln2b + (ll)l*Dd, ph);
        gemm_main(BT, Ff, Dd, ph, Dd, w1 + (ll)l*Dd*Ff, Ff, pf, Ff,
                  b1 + (ll)l*Ff, 2);                             // relu
        gemm_main(BT, Dd, Ff, pf, Ff, w2 + (ll)l*Ff*Dd, Dd, pp, Dd,
                  b2 + (ll)l*Dd, 1);
        add_kernel<<<(BT*Dd)/1024, 256>>>(ph, pp, px);           // x = h2 + f
    }

    ln_kernel<<<BT, 256>>>(px, lnfg, lnfb, ph);
    gemm_main(BT, Vv, Dd, ph, Dd, wlm, Vv, logits, Vv, blm, 1);

    rowloss_kernel<<<BT, 256>>>(logits, tgt, prl);
    lossreduce_kernel<<<1, 256>>>(prl, lossp);
}

// round 14
// speedup vs baseline: 1.0013x; 1.0013x over previous
#include <cuda_runtime.h>
#include <math.h>
#include <float.h>

typedef long long ll;

#define Bb 2
#define Tt 2048
#define BT 4096
#define Dd 1024
#define Hh 16
#define HS 64
#define Ff 4096
#define Vv 32000
#define Ll 8

// ---------------- static scratch (no allocations allowed) ----------------
__device__ float g_x [BT*Dd];
__device__ float g_h [BT*Dd];
__device__ float g_q [BT*Dd];
__device__ float g_k [BT*Dd];
__device__ float g_v [BT*Dd];
__device__ float g_vs[BT*Dd];
__device__ float g_o [BT*Dd];
__device__ float g_p [BT*Dd];
__device__ float g_f [BT*Ff];
__device__ float g_att[134217728];     // B*H*T*T = 512MB
__device__ float g_ci [Bb*Hh*Tt];
__device__ float g_wq [Dd*Dd];
__device__ float g_wk [Dd*Dd];
__device__ float g_wv [Dd*Dd];
__device__ float g_rl [BT];
__device__ float g_loss[4];

// ---------------- reductions ----------------
__device__ __forceinline__ float blockReduceSum(float v){
    __shared__ float sh[33];
    int lane = threadIdx.x & 31, wid = threadIdx.x >> 5;
    #pragma unroll
    for (int o = 16; o; o >>= 1) v += __shfl_xor_sync(0xffffffffu, v, o);
    __syncthreads();
    if (lane == 0) sh[wid] = v;
    __syncthreads();
    if (wid == 0) {
        int nw = (blockDim.x + 31) >> 5;
        float r = (lane < nw) ? sh[lane] : 0.f;
        #pragma unroll
        for (int o = 16; o; o >>= 1) r += __shfl_xor_sync(0xffffffffu, r, o);
        if (lane == 0) sh[32] = r;
    }
    __syncthreads();
    return sh[32];
}

__device__ __forceinline__ float blockReduceMax(float v){
    __shared__ float shm[33];
    int lane = threadIdx.x & 31, wid = threadIdx.x >> 5;
    #pragma unroll
    for (int o = 16; o; o >>= 1) v = fmaxf(v, __shfl_xor_sync(0xffffffffu, v, o));
    __syncthreads();
    if (lane == 0) shm[wid] = v;
    __syncthreads();
    if (wid == 0) {
        int nw = (blockDim.x + 31) >> 5;
        float r = (lane < nw) ? shm[lane] : -FLT_MAX;
        #pragma unroll
        for (int o = 16; o; o >>= 1) r = fmaxf(r, __shfl_xor_sync(0xffffffffu, r, o));
        if (lane == 0) shm[32] = r;
    }
    __syncthreads();
    return shm[32];
}

// ---------------- generic SGEMM (NN) with fused epilogue ----------------
// C[M,N] = A[M,K] * B[K,N]; EPI: 0=none, 1=+bias, 2=relu(+bias)
// batch offset: bz -> zo=bz/zdiv, zi=bz%zdiv ; base += zo*sXo + zi*sXi
// tri!=0: K truncated to bm+BM (causal lower-triangular A)
template<int BM,int BN,int BK,int TM,int TN,int EPI>
__global__ void __launch_bounds__((BM/TM)*(BN/TN))
sgemm_nn(int M,int N,int K,
         const float* __restrict__ A,int lda,
         const float* __restrict__ B,int ldb,
         float* __restrict__ C,int ldc,
         const float* __restrict__ bias,
         int zdiv, ll sAo, ll sAi, ll sBo, ll sBi, ll sCo, ll sCi, int tri)
{
    constexpr int THREADS = (BM/TM)*(BN/TN);
    __shared__ __align__(16) float As[BK][BM];
    __shared__ __align__(16) float Bs[BK][BN];

    int bz = blockIdx.z;
    int zo = bz / zdiv, zi = bz % zdiv;
    A += (ll)zo*sAo + (ll)zi*sAi;
    B += (ll)zo*sBo + (ll)zi*sBi;
    C += (ll)zo*sCo + (ll)zi*sCi;

    int bm = blockIdx.y * BM, bn = blockIdx.x * BN;
    int Keff = tri ? min(K, bm + BM) : K;

    int tid = threadIdx.x;
    int tx = tid % (BN/TN), ty = tid / (BN/TN);

    constexpr int LA = (BM*BK)/(4*THREADS);
    constexpr int LB = (BK*BN)/(4*THREADS);
    constexpr int A_RPP = THREADS/(BK/4);
    constexpr int B_RPP = THREADS/(BN/4);
    int a_c4 = tid % (BK/4), a_r = tid / (BK/4);
    int b_c4 = tid % (BN/4), b_r = tid / (BN/4);

    float acc[TM][TN] = {};

    for (int k0 = 0; k0 < Keff; k0 += BK) {
        #pragma unroll
        for (int p = 0; p < LA; p++) {
            int r = a_r + p * A_RPP;
            float4 v = *(const float4*)&A[(ll)(bm + r)*lda + k0 + a_c4*4];
            As[a_c4*4+0][r] = v.x; As[a_c4*4+1][r] = v.y;
            As[a_c4*4+2][r] = v.z; As[a_c4*4+3][r] = v.w;
        }
        #pragma unroll
        for (int p = 0; p < LB; p++) {
            int r = b_r + p * B_RPP;
            *(float4*)&Bs[r][b_c4*4] = *(const float4*)&B[(ll)(k0 + r)*ldb + bn + b_c4*4];
        }
        __syncthreads();
        #pragma unroll
        for (int kk = 0; kk < BK; kk++) {
            float a[TM], b[TN];
            #pragma unroll
            for (int i = 0; i < TM; i += 4)
                *(float4*)&a[i] = *(const float4*)&As[kk][ty*TM + i];
            #pragma unroll
            for (int j = 0; j < TN; j += 4)
                *(float4*)&b[j] = *(const float4*)&Bs[kk][tx*TN + j];
            #pragma unroll
            for (int i = 0; i < TM; i++)
                #pragma unroll
                for (int j = 0; j < TN; j++)
                    acc[i][j] = fmaf(a[i], b[j], acc[i][j]);
        }
        __syncthreads();
    }

    #pragma unroll
    for (int i = 0; i < TM; i++) {
        int row = bm + ty*TM + i;
        float* crow = C + (ll)row*ldc + bn + tx*TN;
        #pragma unroll
        for (int j0 = 0; j0 < TN; j0 += 4) {
            float4 v;
            v.x = acc[i][j0+0]; v.y = acc[i][j0+1];
            v.z = acc[i][j0+2]; v.w = acc[i][j0+3];
            if (EPI >= 1) {
                float4 bv = *(const float4*)&bias[bn + tx*TN + j0];
                v.x += bv.x; v.y += bv.y; v.z += bv.z; v.w += bv.w;
            }
            if (EPI == 2) {
                v.x = fmaxf(v.x, 0.f); v.y = fmaxf(v.y, 0.f);
                v.z = fmaxf(v.z, 0.f); v.w = fmaxf(v.w, 0.f);
            }
            *(float4*)&crow[j0] = v;
        }
    }
}

// ---------------- attention: E = exp(scale * Q K^T) masked (NT GEMM) ----------------
// grid (T/128, T/128, B*H), 256 threads
__global__ void __launch_bounds__(256)
attn_scores_kernel(const float* __restrict__ Q, const float* __restrict__ Km,
                   float* __restrict__ E)
{
    int bz = blockIdx.z;
    int b = bz >> 4, h = bz & 15;
    const float* Qb = Q + (ll)b*Tt*Dd + h*HS;
    const float* Kb = Km + (ll)b*Tt*Dd + h*HS;
    float* Eb = E + (ll)bz*Tt*Tt;

    int bm = blockIdx.y * 128, bn = blockIdx.x * 128;
    int tid = threadIdx.x;

    if (bn > bm + 127) {  // entire tile above diagonal -> zeros
        for (int i = tid; i < 128*32; i += 256) {
            int r = i >> 5, c4 = i & 31;
            *(float4*)&Eb[(ll)(bm + r)*Tt + bn + c4*4] = make_float4(0.f,0.f,0.f,0.f);
        }
        return;
    }

    __shared__ __align__(16) float As[16][128];
    __shared__ __align__(16) float Bs[16][128];
    int tx = tid & 15, ty = tid >> 4;
    int c4 = tid & 3, rr = tid >> 2;   // 64 rows per pass, 4 cols(f4)
    float acc[8][8] = {};

    for (int k0 = 0; k0 < HS; k0 += 16) {
        #pragma unroll
        for (int p = 0; p < 2; p++) {
            int r = rr + p*64;
            float4 v = *(const float4*)&Qb[(ll)(bm + r)*Dd + k0 + c4*4];
            As[c4*4+0][r] = v.x; As[c4*4+1][r] = v.y; As[c4*4+2][r] = v.z; As[c4*4+3][r] = v.w;
            float4 w = *(const float4*)&Kb[(ll)(bn + r)*Dd + k0 + c4*4];
            Bs[c4*4+0][r] = w.x; Bs[c4*4+1][r] = w.y; Bs[c4*4+2][r] = w.z; Bs[c4*4+3][r] = w.w;
        }
        __syncthreads();
        #pragma unroll
        for (int kk = 0; kk < 16; kk++) {
            float a[8], b2[8];
            #pragma unroll
            for (int i = 0; i < 8; i += 4) *(float4*)&a[i]  = *(const float4*)&As[kk][ty*8 + i];
            #pragma unroll
            for (int j = 0; j < 8; j += 4) *(float4*)&b2[j] = *(const float4*)&Bs[kk][tx*8 + j];
            #pragma unroll
            for (int i = 0; i < 8; i++)
                #pragma unroll
                for (int j = 0; j < 8; j++)
                    acc[i][j] = fmaf(a[i], b2[j], acc[i][j]);
        }
        __syncthreads();
    }

    const float scale = 0.03125f;   // D^-0.5 = 1/32
    #pragma unroll
    for (int i = 0; i < 8; i++) {
        int row = bm + ty*8 + i;
        #pragma unroll
        for (int j0 = 0; j0 < 8; j0 += 4) {
            float4 v;
            int col = bn + tx*8 + j0;
            v.x = (col+0 <= row) ? __expf(scale*acc[i][j0+0]) : 0.f;
            v.y = (col+1 <= row) ? __expf(scale*acc[i][j0+1]) : 0.f;
            v.z = (col+2 <= row) ? __expf(scale*acc[i][j0+2]) : 0.f;
            v.w = (col+3 <= row) ? __expf(scale*acc[i][j0+3]) : 0.f;
            *(float4*)&Eb[(ll)row*Tt + col] = v;
        }
    }
}

// ---------------- column-sum inverse over query axis ----------------
__global__ void colinv_kernel(const float* __restrict__ E, float* __restrict__ ci)
{
    int bz = blockIdx.y;
    int s = blockIdx.x * 256 + threadIdx.x;
    const float* Eb = E + (ll)bz*Tt*Tt;
    int t0 = blockIdx.x * 256;  // rows below block start are all zero
    float sum = 0.f;
    for (int t = t0; t < Tt; t++) sum += Eb[(ll)t*Tt + s];
    ci[bz*Tt + s] = 1.f / sum;
}

// ---------------- v' = v / colsum ----------------
__global__ void vscale_kernel(const float* __restrict__ v2, const float* __restrict__ ci,
                              float* __restrict__ vs)
{
    ll i4 = (ll)blockIdx.x * 256 + threadIdx.x;
    ll i = i4 * 4;
    int bt = (int)(i >> 10);
    int d  = (int)(i & 1023);
    int h = d >> 6;
    int b = bt >> 11, t = bt & 2047;
    float c = ci[((b*Hh + h) << 11) + t];
    float4 v = ((const float4*)v2)[i4];
    v.x *= c; v.y *= c; v.z *= c; v.w *= c;
    ((float4*)vs)[i4] = v;
}

// ---------------- layernorm (one block per row, D=1024, 256 threads) ----------------
__global__ void ln_kernel(const float* __restrict__ x, const float* __restrict__ g,
                          const float* __restrict__ bta, float* __restrict__ y)
{
    int row = blockIdx.x, tid = threadIdx.x;
    float4 v = ((const float4*)(x + (ll)row*Dd))[tid];
    float mean = blockReduceSum(v.x + v.y + v.z + v.w) * (1.f/1024.f);
    float dx = v.x - mean, dy = v.y - mean, dz = v.z - mean, dw = v.w - mean;
    float var = blockReduceSum(dx*dx + dy*dy + dz*dz + dw*dw) * (1.f/1024.f);
    float rstd = rsqrtf(var + 1e-5f);
    float4 gv = ((const float4*)g)[tid];
    float4 bv = ((const float4*)bta)[tid];
    float4 o;
    o.x = dx*rstd*gv.x + bv.x; o.y = dy*rstd*gv.y + bv.y;
    o.z = dz*rstd*gv.z + bv.z; o.w = dw*rstd*gv.w + bv.w;
    ((float4*)(y + (ll)row*Dd))[tid] = o;
}

// ---------------- embedding ----------------
__global__ void embed_kernel(const int* __restrict__ idx, const float* __restrict__ tok,
                             const float* __restrict__ pos, float* __restrict__ x)
{
    int bt = blockIdx.x, tid = threadIdx.x;
    int t = bt & (Tt - 1);
    int token = idx[bt];
    float4 a = ((const float4*)(tok + (ll)token*Dd))[tid];
    float4 p = ((const float4*)(pos + (ll)t*Dd))[tid];
    float4 o = make_float4(a.x+p.x, a.y+p.y, a.z+p.z, a.w+p.w);
    ((float4*)(x + (ll)bt*Dd))[tid] = o;
}

// ---------------- elementwise add ----------------
__global__ void add_kernel(const float* __restrict__ a, const float* __restrict__ b,
                           float* __restrict__ c)
{
    ll i = (ll)blockIdx.x * 256 + threadIdx.x;
    float4 av = ((const float4*)a)[i];
    float4 bv = ((const float4*)b)[i];
    ((float4*)c)[i] = make_float4(av.x+bv.x, av.y+bv.y, av.z+bv.z, av.w+bv.w);
}

// ---------------- pack [H,D,hs] -> [D, H*hs] for q/k/v ----------------
__global__ void pack_qkv_kernel(const float* __restrict__ wq, const float* __restrict__ wk,
                                const float* __restrict__ wv,
                                float* __restrict__ pq, float* __restrict__ pk,
                                float* __restrict__ pv)
{
    int n = blockIdx.x * 256 + threadIdx.x;  // over D*D
    int d = n >> 10, c = n & 1023;
    int h = c >> 6, e = c & 63;
    ll src = ((ll)h*Dd + d)*64 + e;
    pq[n] = wq[src]; pk[n] = wk[src]; pv[n] = wv[src];
}

// ---------------- per-row cross-entropy ----------------
__global__ void rowloss_kernel(const float* __restrict__ logits, const int* __restrict__ tg,
                               float* __restrict__ rl)
{
    int row = blockIdx.x, tid = threadIdx.x;
    const float* lr = logits + (ll)row * Vv;
    float mx = -FLT_MAX;
    for (int i = tid; i < Vv; i += 256) mx = fmaxf(mx, lr[i]);
    mx = blockReduceMax(mx);
    float se = 0.f;
    for (int i = tid; i < Vv; i += 256) se += __expf(lr[i] - mx);
    se = blockReduceSum(se);
    if (tid == 0) rl[row] = mx + logf(se) - lr[tg[row]];
}

__global__ void lossreduce_kernel(const float* __restrict__ rl, float* __restrict__ out)
{
    float s = 0.f;
    for (int i = threadIdx.x; i < BT; i += 256) s += rl[i];
    s = blockReduceSum(s);
    if (threadIdx.x == 0) out[0] = s * (1.f / (float)BT);
}

// ---------------- host-side GEMM dispatch ----------------
static void gemm_main(int M, int N, int K, const float* A, int lda,
                      const float* B, int ldb, float* C, int ldc,
                      const float* bias, int epi)
{
    dim3 grid(N/128, M/128, 1);
    if (epi == 0)
        sgemm_nn<128,128,16,8,8,0><<<grid,256>>>(M,N,K,A,lda,B,ldb,C,ldc,bias,1,0,0,0,0,0,0,0);
    else if (epi == 1)
        sgemm_nn<128,128,16,8,8,1><<<grid,256>>>(M,N,K,A,lda,B,ldb,C,ldc,bias,1,0,0,0,0,0,0,0);
    else
        sgemm_nn<128,128,16,8,8,2><<<grid,256>>>(M,N,K,A,lda,B,ldb,C,ldc,bias,1,0,0,0,0,0,0,0);
}

extern "C" void kernel_launch(void* const* d_in, const int* in_sizes, int n_in,
                              void* d_out, int out_size)
{
    const int*   idx   = (const int*)  d_in[0];
    const int*   tgt   = (const int*)  d_in[1];
    const float* tok   = (const float*)d_in[2];
    const float* pos   = (const float*)d_in[3];
    const float* wq    = (const float*)d_in[4];
    const float* wk    = (const float*)d_in[5];
    const float* wv    = (const float*)d_in[6];
    const float* wproj = (const float*)d_in[7];
    const float* bproj = (const float*)d_in[8];
    const float* ln1g  = (const float*)d_in[9];
    const float* ln1b  = (const float*)d_in[10];
    const float* ln2g  = (const float*)d_in[11];
    const float* ln2b  = (const float*)d_in[12];
    const float* w1    = (const float*)d_in[13];
    const float* b1    = (const float*)d_in[14];
    const float* w2    = (const float*)d_in[15];
    const float* b2    = (const float*)d_in[16];
    const float* lnfg  = (const float*)d_in[17];
    const float* lnfb  = (const float*)d_in[18];
    const float* wlm   = (const float*)d_in[19];
    const float* blm   = (const float*)d_in[20];

    float *px,*ph,*pq,*pk,*pv,*pvs,*po,*pp,*pf,*pe,*pci,*pwq,*pwk,*pwv,*prl,*plo;
    cudaGetSymbolAddress((void**)&px,  g_x);
    cudaGetSymbolAddress((void**)&ph,  g_h);
    cudaGetSymbolAddress((void**)&pq,  g_q);
    cudaGetSymbolAddress((void**)&pk,  g_k);
    cudaGetSymbolAddress((void**)&pv,  g_v);
    cudaGetSymbolAddress((void**)&pvs, g_vs);
    cudaGetSymbolAddress((void**)&po,  g_o);
    cudaGetSymbolAddress((void**)&pp,  g_p);
    cudaGetSymbolAddress((void**)&pf,  g_f);
    cudaGetSymbolAddress((void**)&pe,  g_att);
    cudaGetSymbolAddress((void**)&pci, g_ci);
    cudaGetSymbolAddress((void**)&pwq, g_wq);
    cudaGetSymbolAddress((void**)&pwk, g_wk);
    cudaGetSymbolAddress((void**)&pwv, g_wv);
    cudaGetSymbolAddress((void**)&prl, g_rl);
    cudaGetSymbolAddress((void**)&plo, g_loss);

    float* out = (float*)d_out;
    const ll NL = (ll)BT * Vv;               // 131,072,000
    float* logits = (out_size >= (int)NL) ? out : pe;   // reuse E scratch if needed
    float* lossp  = plo;
    if ((ll)out_size == NL + 1) lossp = out + NL;
    else if (out_size == 1)     lossp = out;

    embed_kernel<<<BT, 256>>>(idx, tok, pos, px);

    for (int l = 0; l < Ll; l++) {
        ln_kernel<<<BT, 256>>>(px, ln1g + (ll)l*Dd, ln1b + (ll)l*Dd, ph);

        pack_qkv_kernel<<<(Dd*Dd)/256, 256>>>(
            wq + (ll)l*Hh*Dd*HS, wk + (ll)l*Hh*Dd*HS, wv + (ll)l*Hh*Dd*HS,
            pwq, pwk, pwv);

        gemm_main(BT, Dd, Dd, ph, Dd, pwq, Dd, pq, Dd, nullptr, 0);
        gemm_main(BT, Dd, Dd, ph, Dd, pwk, Dd, pk, Dd, nullptr, 0);
        gemm_main(BT, Dd, Dd, ph, Dd, pwv, Dd, pv, Dd, nullptr, 0);

        attn_scores_kernel<<<dim3(Tt/128, Tt/128, Bb*Hh), 256>>>(pq, pk, pe);
        colinv_kernel<<<dim3(Tt/256, Bb*Hh), 256>>>(pe, pci);
        vscale_kernel<<<(BT*Dd)/1024, 256>>>(pv, pci, pvs);

        // O = E @ V'   batched over (b,h): M=T, N=64, K=T, causal K truncation
        {
            dim3 grid(1, Tt/128, Bb*Hh);
            sgemm_nn<128,64,16,8,8,0><<<grid,128>>>(
                Tt, 64, Tt,
                pe, Tt,
                pvs, Dd,
                po, Dd,
                nullptr,
                Hh,
                (ll)Hh*Tt*Tt, (ll)Tt*Tt,   // A: bz*T*T
                (ll)Tt*Dd, 64LL,           // B: b*T*D + h*64
                (ll)Tt*Dd, 64LL,           // C: b*T*D + h*64
                1);
        }

        gemm_main(BT, Dd, Dd, po, Dd, wproj + (ll)l*Dd*Dd, Dd, pp, Dd,
                  bproj + (ll)l*Dd, 1);
        add_kernel<<<(BT*Dd)/1024, 256>>>(ph, pp, px);           // x = h + o

        ln_kernel<<<BT, 256>>>(px, ln2g + (ll)l*Dd, ln2b + (ll)l*Dd, ph);
        gemm_main(BT, Ff, Dd, ph, Dd, w1 + (ll)l*Dd*Ff, Ff, pf, Ff,
                  b1 + (ll)l*Ff, 2);                             // relu
        gemm_main(BT, Dd, Ff, pf, Ff, w2 + (ll)l*Ff*Dd, Dd, pp, Dd,
                  b2 + (ll)l*Dd, 1);
        add_kernel<<<(BT*Dd)/1024, 256>>>(ph, pp, px);           // x = h2 + f
    }

    ln_kernel<<<BT, 256>>>(px, lnfg, lnfb, ph);
    gemm_main(BT, Vv, Dd, ph, Dd, wlm, Vv, logits, Vv, blm, 1);

    rowloss_kernel<<<BT, 256>>>(logits, tgt, prl);
    lossreduce_kernel<<<1, 256>>>(prl, lossp);
}

// round 15
// speedup vs baseline: 1.0018x; 1.0005x over previous
#include <cuda_runtime.h>
#include <math.h>
#include <float.h>

typedef long long ll;

#define Bb 2
#define Tt 2048
#define BT 4096
#define Dd 1024
#define Hh 16
#define HS 64
#define Ff 4096
#define Vv 32000
#define Ll 8

// ---------------- static scratch (no allocations allowed) ----------------
__device__ float g_x [BT*Dd];
__device__ float g_h [BT*Dd];
__device__ float g_q [BT*Dd];
__device__ float g_k [BT*Dd];
__device__ float g_v [BT*Dd];
__device__ float g_vs[BT*Dd];
__device__ float g_o [BT*Dd];
__device__ float g_p [BT*Dd];
__device__ float g_f [BT*Ff];
__device__ float g_att[134217728];     // B*H*T*T = 512MB
__device__ float g_ci [Bb*Hh*Tt];
__device__ float g_wq [Dd*Dd];
__device__ float g_wk [Dd*Dd];
__device__ float g_wv [Dd*Dd];
__device__ float g_rl [BT];
__device__ float g_loss[4];

// ---------------- reductions ----------------
__device__ __forceinline__ float blockReduceSum(float v){
    __shared__ float sh[33];
    int lane = threadIdx.x & 31, wid = threadIdx.x >> 5;
    #pragma unroll
    for (int o = 16; o; o >>= 1) v += __shfl_xor_sync(0xffffffffu, v, o);
    __syncthreads();
    if (lane == 0) sh[wid] = v;
    __syncthreads();
    if (wid == 0) {
        int nw = (blockDim.x + 31) >> 5;
        float r = (lane < nw) ? sh[lane] : 0.f;
        #pragma unroll
        for (int o = 16; o; o >>= 1) r += __shfl_xor_sync(0xffffffffu, r, o);
        if (lane == 0) sh[32] = r;
    }
    __syncthreads();
    return sh[32];
}

__device__ __forceinline__ float blockReduceMax(float v){
    __shared__ float shm[33];
    int lane = threadIdx.x & 31, wid = threadIdx.x >> 5;
    #pragma unroll
    for (int o = 16; o; o >>= 1) v = fmaxf(v, __shfl_xor_sync(0xffffffffu, v, o));
    __syncthreads();
    if (lane == 0) shm[wid] = v;
    __syncthreads();
    if (wid == 0) {
        int nw = (blockDim.x + 31) >> 5;
        float r = (lane < nw) ? shm[lane] : -FLT_MAX;
        #pragma unroll
        for (int o = 16; o; o >>= 1) r = fmaxf(r, __shfl_xor_sync(0xffffffffu, r, o));
        if (lane == 0) shm[32] = r;
    }
    __syncthreads();
    return shm[32];
}

// ---------------- generic SGEMM (NN) with fused epilogue ----------------
// C[M,N] = A[M,K] * B[K,N]; EPI: 0=none, 1=+bias, 2=relu(+bias)
// batch offset: bz -> zo=bz/zdiv, zi=bz%zdiv ; base += zo*sXo + zi*sXi
// tri!=0: K truncated to bm+BM (causal lower-triangular A)
template<int BM,int BN,int BK,int TM,int TN,int EPI>
__global__ void __launch_bounds__((BM/TM)*(BN/TN))
sgemm_nn(int M,int N,int K,
         const float* __restrict__ A,int lda,
         const float* __restrict__ B,int ldb,
         float* __restrict__ C,int ldc,
         const float* __restrict__ bias,
         int zdiv, ll sAo, ll sAi, ll sBo, ll sBi, ll sCo, ll sCi, int tri)
{
    constexpr int THREADS = (BM/TM)*(BN/TN);
    __shared__ __align__(16) float As[BK][BM];
    __shared__ __align__(16) float Bs[BK][BN];

    int bz = blockIdx.z;
    int zo = bz / zdiv, zi = bz % zdiv;
    A += (ll)zo*sAo + (ll)zi*sAi;
    B += (ll)zo*sBo + (ll)zi*sBi;
    C += (ll)zo*sCo + (ll)zi*sCi;

    int bm = blockIdx.y * BM, bn = blockIdx.x * BN;
    int Keff = tri ? min(K, bm + BM) : K;

    int tid = threadIdx.x;
    int tx = tid % (BN/TN), ty = tid / (BN/TN);

    constexpr int LA = (BM*BK)/(4*THREADS);
    constexpr int LB = (BK*BN)/(4*THREADS);
    constexpr int A_RPP = THREADS/(BK/4);
    constexpr int B_RPP = THREADS/(BN/4);
    int a_c4 = tid % (BK/4), a_r = tid / (BK/4);
    int b_c4 = tid % (BN/4), b_r = tid / (BN/4);

    float acc[TM][TN] = {};

    for (int k0 = 0; k0 < Keff; k0 += BK) {
        #pragma unroll
        for (int p = 0; p < LA; p++) {
            int r = a_r + p * A_RPP;
            float4 v = *(const float4*)&A[(ll)(bm + r)*lda + k0 + a_c4*4];
            As[a_c4*4+0][r] = v.x; As[a_c4*4+1][r] = v.y;
            As[a_c4*4+2][r] = v.z; As[a_c4*4+3][r] = v.w;
        }
        #pragma unroll
        for (int p = 0; p < LB; p++) {
            int r = b_r + p * B_RPP;
            *(float4*)&Bs[r][b_c4*4] = *(const float4*)&B[(ll)(k0 + r)*ldb + bn + b_c4*4];
        }
        __syncthreads();
        #pragma unroll
        for (int kk = 0; kk < BK; kk++) {
            float a[TM], b[TN];
            #pragma unroll
            for (int i = 0; i < TM; i += 4)
                *(float4*)&a[i] = *(const float4*)&As[kk][ty*TM + i];
            #pragma unroll
            for (int j = 0; j < TN; j += 4)
                *(float4*)&b[j] = *(const float4*)&Bs[kk][tx*TN + j];
            #pragma unroll
            for (int i = 0; i < TM; i++)
                #pragma unroll
                for (int j = 0; j < TN; j++)
                    acc[i][j] = fmaf(a[i], b[j], acc[i][j]);
        }
        __syncthreads();
    }

    #pragma unroll
    for (int i = 0; i < TM; i++) {
        int row = bm + ty*TM + i;
        float* crow = C + (ll)row*ldc + bn + tx*TN;
        #pragma unroll
        for (int j0 = 0; j0 < TN; j0 += 4) {
            float4 v;
            v.x = acc[i][j0+0]; v.y = acc[i][j0+1];
            v.z = acc[i][j0+2]; v.w = acc[i][j0+3];
            if (EPI >= 1) {
                float4 bv = *(const float4*)&bias[bn + tx*TN + j0];
                v.x += bv.x; v.y += bv.y; v.z += bv.z; v.w += bv.w;
            }
            if (EPI == 2) {
                v.x = fmaxf(v.x, 0.f); v.y = fmaxf(v.y, 0.f);
                v.z = fmaxf(v.z, 0.f); v.w = fmaxf(v.w, 0.f);
            }
            *(float4*)&crow[j0] = v;
        }
    }
}

// ---------------- attention: E = exp(scale * Q K^T) masked (NT GEMM) ----------------
// grid (T/128, T/128, B*H), 256 threads
__global__ void __launch_bounds__(256)
attn_scores_kernel(const float* __restrict__ Q, const float* __restrict__ Km,
                   float* __restrict__ E)
{
    int bz = blockIdx.z;
    int b = bz >> 4, h = bz & 15;
    const float* Qb = Q + (ll)b*Tt*Dd + h*HS;
    const float* Kb = Km + (ll)b*Tt*Dd + h*HS;
    float* Eb = E + (ll)bz*Tt*Tt;

    int bm = blockIdx.y * 128, bn = blockIdx.x * 128;
    int tid = threadIdx.x;

    if (bn > bm + 127) {  // entire tile above diagonal -> zeros
        for (int i = tid; i < 128*32; i += 256) {
            int r = i >> 5, c4 = i & 31;
            *(float4*)&Eb[(ll)(bm + r)*Tt + bn + c4*4] = make_float4(0.f,0.f,0.f,0.f);
        }
        return;
    }

    __shared__ __align__(16) float As[16][128];
    __shared__ __align__(16) float Bs[16][128];
    int tx = tid & 15, ty = tid >> 4;
    int c4 = tid & 3, rr = tid >> 2;   // 64 rows per pass, 4 cols(f4)
    float acc[8][8] = {};

    for (int k0 = 0; k0 < HS; k0 += 16) {
        #pragma unroll
        for (int p = 0; p < 2; p++) {
            int r = rr + p*64;
            float4 v = *(const float4*)&Qb[(ll)(bm + r)*Dd + k0 + c4*4];
            As[c4*4+0][r] = v.x; As[c4*4+1][r] = v.y; As[c4*4+2][r] = v.z; As[c4*4+3][r] = v.w;
            float4 w = *(const float4*)&Kb[(ll)(bn + r)*Dd + k0 + c4*4];
            Bs[c4*4+0][r] = w.x; Bs[c4*4+1][r] = w.y; Bs[c4*4+2][r] = w.z; Bs[c4*4+3][r] = w.w;
        }
        __syncthreads();
        #pragma unroll
        for (int kk = 0; kk < 16; kk++) {
            float a[8], b2[8];
            #pragma unroll
            for (int i = 0; i < 8; i += 4) *(float4*)&a[i]  = *(const float4*)&As[kk][ty*8 + i];
            #pragma unroll
            for (int j = 0; j < 8; j += 4) *(float4*)&b2[j] = *(const float4*)&Bs[kk][tx*8 + j];
            #pragma unroll
            for (int i = 0; i < 8; i++)
                #pragma unroll
                for (int j = 0; j < 8; j++)
                    acc[i][j] = fmaf(a[i], b2[j], acc[i][j]);
        }
        __syncthreads();
    }

    const float scale = 0.03125f;   // D^-0.5 = 1/32
    #pragma unroll
    for (int i = 0; i < 8; i++) {
        int row = bm + ty*8 + i;
        #pragma unroll
        for (int j0 = 0; j0 < 8; j0 += 4) {
            float4 v;
            int col = bn + tx*8 + j0;
            v.x = (col+0 <= row) ? __expf(scale*acc[i][j0+0]) : 0.f;
            v.y = (col+1 <= row) ? __expf(scale*acc[i][j0+1]) : 0.f;
            v.z = (col+2 <= row) ? __expf(scale*acc[i][j0+2]) : 0.f;
            v.w = (col+3 <= row) ? __expf(scale*acc[i][j0+3]) : 0.f;
            *(float4*)&Eb[(ll)row*Tt + col] = v;
        }
    }
}

// ---------------- column-sum inverse over query axis ----------------
__global__ void colinv_kernel(const float* __restrict__ E, float* __restrict__ ci)
{
    int bz = blockIdx.y;
    int s = blockIdx.x * 256 + threadIdx.x;
    const float* Eb = E + (ll)bz*Tt*Tt;
    int t0 = blockIdx.x * 256;  // rows below block start are all zero
    float sum = 0.f;
    for (int t = t0; t < Tt; t++) sum += Eb[(ll)t*Tt + s];
    ci[bz*Tt + s] = 1.f / sum;
}

// ---------------- v' = v / colsum ----------------
__global__ void vscale_kernel(const float* __restrict__ v2, const float* __restrict__ ci,
                              float* __restrict__ vs)
{
    ll i4 = (ll)blockIdx.x * 256 + threadIdx.x;
    ll i = i4 * 4;
    int bt = (int)(i >> 10);
    int d  = (int)(i & 1023);
    int h = d >> 6;
    int b = bt >> 11, t = bt & 2047;
    float c = ci[((b*Hh + h) << 11) + t];
    float4 v = ((const float4*)v2)[i4];
    v.x *= c; v.y *= c; v.z *= c; v.w *= c;
    ((float4*)vs)[i4] = v;
}

// ---------------- layernorm (one block per row, D=1024, 256 threads) ----------------
__global__ void ln_kernel(const float* __restrict__ x, const float* __restrict__ g,
                          const float* __restrict__ bta, float* __restrict__ y)
{
    int row = blockIdx.x, tid = threadIdx.x;
    float4 v = ((const float4*)(x + (ll)row*Dd))[tid];
    float mean = blockReduceSum(v.x + v.y + v.z + v.w) * (1.f/1024.f);
    float dx = v.x - mean, dy = v.y - mean, dz = v.z - mean, dw = v.w - mean;
    float var = blockReduceSum(dx*dx + dy*dy + dz*dz + dw*dw) * (1.f/1024.f);
    float rstd = rsqrtf(var + 1e-5f);
    float4 gv = ((const float4*)g)[tid];
    float4 bv = ((const float4*)bta)[tid];
    float4 o;
    o.x = dx*rstd*gv.x + bv.x; o.y = dy*rstd*gv.y + bv.y;
    o.z = dz*rstd*gv.z + bv.z; o.w = dw*rstd*gv.w + bv.w;
    ((float4*)(y + (ll)row*Dd))[tid] = o;
}

// ---------------- embedding ----------------
__global__ void embed_kernel(const int* __restrict__ idx, const float* __restrict__ tok,
                             const float* __restrict__ pos, float* __restrict__ x)
{
    int bt = blockIdx.x, tid = threadIdx.x;
    int t = bt & (Tt - 1);
    int token = idx[bt];
    float4 a = ((const float4*)(tok + (ll)token*Dd))[tid];
    float4 p = ((const float4*)(pos + (ll)t*Dd))[tid];
    float4 o = make_float4(a.x+p.x, a.y+p.y, a.z+p.z, a.w+p.w);
    ((float4*)(x + (ll)bt*Dd))[tid] = o;
}

// ---------------- elementwise add ----------------
__global__ void add_kernel(const float* __restrict__ a, const float* __restrict__ b,
                           float* __restrict__ c)
{
    ll i = (ll)blockIdx.x * 256 + threadIdx.x;
    float4 av = ((const float4*)a)[i];
    float4 bv = ((const float4*)b)[i];
    ((float4*)c)[i] = make_float4(av.x+bv.x, av.y+bv.y, av.z+bv.z, av.w+bv.w);
}

// ---------------- pack [H,D,hs] -> [D, H*hs] for q/k/v ----------------
__global__ void pack_qkv_kernel(const float* __restrict__ wq, const float* __restrict__ wk,
                                const float* __restrict__ wv,
                                float* __restrict__ pq, float* __restrict__ pk,
                                float* __restrict__ pv)
{
    int n = blockIdx.x * 256 + threadIdx.x;  // over D*D
    int d = n >> 10, c = n & 1023;
    int h = c >> 6, e = c & 63;
    ll src = ((ll)h*Dd + d)*64 + e;
    pq[n] = wq[src]; pk[n] = wk[src]; pv[n] = wv[src];
}

// ---------------- per-row cross-entropy ----------------
__global__ void rowloss_kernel(const float* __restrict__ logits, const int* __restrict__ tg,
                               float* __restrict__ rl)
{
    int row = blockIdx.x, tid = threadIdx.x;
    const float* lr = logits + (ll)row * Vv;
    float mx = -FLT_MAX;
    for (int i = tid; i < Vv; i += 256) mx = fmaxf(mx, lr[i]);
    mx = blockReduceMax(mx);
    float se = 0.f;
    for (int i = tid; i < Vv; i += 256) se += __expf(lr[i] - mx);
    se = blockReduceSum(se);
    if (tid == 0) rl[row] = mx + logf(se) - lr[tg[row]];
}

__global__ void lossreduce_kernel(const float* __restrict__ rl, float* __restrict__ out)
{
    float s = 0.f;
    for (int i = threadIdx.x; i < BT; i += 256) s += rl[i];
    s = blockReduceSum(s);
    if (threadIdx.x == 0) out[0] = s * (1.f / (float)BT);
}

// ---------------- host-side GEMM dispatch ----------------
static void gemm_main(int M, int N, int K, const float* A, int lda,
                      const float* B, int ldb, float* C, int ldc,
                      const float* bias, int epi)
{
    dim3 grid(N/128, M/128, 1);
    if (epi == 0)
        sgemm_nn<128,128,16,8,8,0><<<grid,256>>>(M,N,K,A,lda,B,ldb,C,ldc,bias,1,0,0,0,0,0,0,0);
    else if (epi == 1)
        sgemm_nn<128,128,16,8,8,1><<<grid,256>>>(M,N,K,A,lda,B,ldb,C,ldc,bias,1,0,0,0,0,0,0,0);
    else
        sgemm_nn<128,128,16,8,8,2><<<grid,256>>>(M,N,K,A,lda,B,ldb,C,ldc,bias,1,0,0,0,0,0,0,0);
}

extern "C" void kernel_launch(void* const* d_in, const int* in_sizes, int n_in,
                              void* d_out, int out_size)
{
    const int*   idx   = (const int*)  d_in[0];
    const int*   tgt   = (const int*)  d_in[1];
    const float* tok   = (const float*)d_in[2];
    const float* pos   = (const float*)d_in[3];
    const float* wq    = (const float*)d_in[4];
    const float* wk    = (const float*)d_in[5];
    const float* wv    = (const float*)d_in[6];
    const float* wproj = (const float*)d_in[7];
    const float* bproj = (const float*)d_in[8];
    const float* ln1g  = (const float*)d_in[9];
    const float* ln1b  = (const float*)d_in[10];
    const float* ln2g  = (const float*)d_in[11];
    const float* ln2b  = (const float*)d_in[12];
    const float* w1    = (const float*)d_in[13];
    const float* b1    = (const float*)d_in[14];
    const float* w2    = (const float*)d_in[15];
    const float* b2    = (const float*)d_in[16];
    const float* lnfg  = (const float*)d_in[17];
    const float* lnfb  = (const float*)d_in[18];
    const float* wlm   = (const float*)d_in[19];
    const float* blm   = (const float*)d_in[20];

    float *px,*ph,*pq,*pk,*pv,*pvs,*po,*pp,*pf,*pe,*pci,*pwq,*pwk,*pwv,*prl,*plo;
    cudaGetSymbolAddress((void**)&px,  g_x);
    cudaGetSymbolAddress((void**)&ph,  g_h);
    cudaGetSymbolAddress((void**)&pq,  g_q);
    cudaGetSymbolAddress((void**)&pk,  g_k);
    cudaGetSymbolAddress((void**)&pv,  g_v);
    cudaGetSymbolAddress((void**)&pvs, g_vs);
    cudaGetSymbolAddress((void**)&po,  g_o);
    cudaGetSymbolAddress((void**)&pp,  g_p);
    cudaGetSymbolAddress((void**)&pf,  g_f);
    cudaGetSymbolAddress((void**)&pe,  g_att);
    cudaGetSymbolAddress((void**)&pci, g_ci);
    cudaGetSymbolAddress((void**)&pwq, g_wq);
    cudaGetSymbolAddress((void**)&pwk, g_wk);
    cudaGetSymbolAddress((void**)&pwv, g_wv);
    cudaGetSymbolAddress((void**)&prl, g_rl);
    cudaGetSymbolAddress((void**)&plo, g_loss);

    float* out = (float*)d_out;
    const ll NL = (ll)BT * Vv;               // 131,072,000
    float* logits = (out_size >= (int)NL) ? out : pe;   // reuse E scratch if needed
    float* lossp  = plo;
    if ((ll)out_size == NL + 1) lossp = out + NL;
    else if (out_size == 1)     lossp = out;

    embed_kernel<<<BT, 256>>>(idx, tok, pos, px);

    for (int l = 0; l < Ll; l++) {
        ln_kernel<<<BT, 256>>>(px, ln1g + (ll)l*Dd, ln1b + (ll)l*Dd, ph);

        pack_qkv_kernel<<<(Dd*Dd)/256, 256>>>(
            wq + (ll)l*Hh*Dd*HS, wk + (ll)l*Hh*Dd*HS, wv + (ll)l*Hh*Dd*HS,
            pwq, pwk, pwv);

        gemm_main(BT, Dd, Dd, ph, Dd, pwq, Dd, pq, Dd, nullptr, 0);
        gemm_main(BT, Dd, Dd, ph, Dd, pwk, Dd, pk, Dd, nullptr, 0);
        gemm_main(BT, Dd, Dd, ph, Dd, pwv, Dd, pv, Dd, nullptr, 0);

        attn_scores_kernel<<<dim3(Tt/128, Tt/128, Bb*Hh), 256>>>(pq, pk, pe);
        colinv_kernel<<<dim3(Tt/256, Bb*Hh), 256>>>(pe, pci);
        vscale_kernel<<<(BT*Dd)/1024, 256>>>(pv, pci, pvs);

        // O = E @ V'   batched over (b,h): M=T, N=64, K=T, causal K truncation
        {
            dim3 grid(1, Tt/128, Bb*Hh);
            sgemm_nn<128,64,16,8,8,0><<<grid,128>>>(
                Tt, 64, Tt,
                pe, Tt,
                pvs, Dd,
                po, Dd,
                nullptr,
                Hh,
                (ll)Hh*Tt*Tt, (ll)Tt*Tt,   // A: bz*T*T
                (ll)Tt*Dd, 64LL,           // B: b*T*D + h*64
                (ll)Tt*Dd, 64LL,           // C: b*T*D + h*64
                1);
        }

        gemm_main(BT, Dd, Dd, po, Dd, wproj + (ll)l*Dd*Dd, Dd, pp, Dd,
                  bproj + (ll)l*Dd, 1);
        add_kernel<<<(BT*Dd)/1024, 256>>>(ph, pp, px);           // x = h + o

        ln_kernel<<<BT, 256>>>(px, ln2g + (ll)l*Dd, ln2b + (ll)l*Dd, ph);
        gemm_main(BT, Ff, Dd, ph, Dd, w1 + (ll)l*Dd*Ff, Ff, pf, Ff,
                  b1 + (ll)l*Ff, 2);                             // relu
        gemm_main(BT, Dd, Ff, pf, Ff, w2 + (ll)l*Ff*Dd, Dd, pp, Dd,
                  b2 + (ll)l*Dd, 1);
        add_kernel<<<(BT*Dd)/1024, 256>>>(ph, pp, px);           // x = h2 + f
    }

    ln_kernel<<<BT, 256>>>(px, lnfg, lnfb, ph);
    gemm_main(BT, Vv, Dd, ph, Dd, wlm, Vv, logits, Vv, blm, 1);

    rowloss_kernel<<<BT, 256>>>(logits, tgt, prl);
    lossreduce_kernel<<<1, 256>>>(prl, lossp);
}

// round 16
// speedup vs baseline: 1.0021x; 1.0003x over previous
#include <cuda_runtime.h>
#include <math.h>
#include <float.h>

typedef long long ll;

#define Bb 2
#define Tt 2048
#define BT 4096
#define Dd 1024
#define Hh 16
#define HS 64
#define Ff 4096
#define Vv 32000
#define Ll 8

// ---------------- static scratch (no allocations allowed) ----------------
__device__ float g_x [BT*Dd];
__device__ float g_h [BT*Dd];
__device__ float g_q [BT*Dd];
__device__ float g_k [BT*Dd];
__device__ float g_v [BT*Dd];
__device__ float g_vs[BT*Dd];
__device__ float g_o [BT*Dd];
__device__ float g_p [BT*Dd];
__device__ float g_f [BT*Ff];
__device__ float g_att[134217728];     // B*H*T*T = 512MB
__device__ float g_ci [Bb*Hh*Tt];
__device__ float g_wq [Dd*Dd];
__device__ float g_wk [Dd*Dd];
__device__ float g_wv [Dd*Dd];
__device__ float g_rl [BT];
__device__ float g_loss[4];

// ---------------- reductions ----------------
__device__ __forceinline__ float blockReduceSum(float v){
    __shared__ float sh[33];
    int lane = threadIdx.x & 31, wid = threadIdx.x >> 5;
    #pragma unroll
    for (int o = 16; o; o >>= 1) v += __shfl_xor_sync(0xffffffffu, v, o);
    __syncthreads();
    if (lane == 0) sh[wid] = v;
    __syncthreads();
    if (wid == 0) {
        int nw = (blockDim.x + 31) >> 5;
        float r = (lane < nw) ? sh[lane] : 0.f;
        #pragma unroll
        for (int o = 16; o; o >>= 1) r += __shfl_xor_sync(0xffffffffu, r, o);
        if (lane == 0) sh[32] = r;
    }
    __syncthreads();
    return sh[32];
}

__device__ __forceinline__ float blockReduceMax(float v){
    __shared__ float shm[33];
    int lane = threadIdx.x & 31, wid = threadIdx.x >> 5;
    #pragma unroll
    for (int o = 16; o; o >>= 1) v = fmaxf(v, __shfl_xor_sync(0xffffffffu, v, o));
    __syncthreads();
    if (lane == 0) shm[wid] = v;
    __syncthreads();
    if (wid == 0) {
        int nw = (blockDim.x + 31) >> 5;
        float r = (lane < nw) ? shm[lane] : -FLT_MAX;
        #pragma unroll
        for (int o = 16; o; o >>= 1) r = fmaxf(r, __shfl_xor_sync(0xffffffffu, r, o));
        if (lane == 0) shm[32] = r;
    }
    __syncthreads();
    return shm[32];
}

// ---------------- generic SGEMM (NN) with fused epilogue ----------------
// C[M,N] = A[M,K] * B[K,N]; EPI: 0=none, 1=+bias, 2=relu(+bias)
// batch offset: bz -> zo=bz/zdiv, zi=bz%zdiv ; base += zo*sXo + zi*sXi
// tri!=0: K truncated to bm+BM (causal lower-triangular A)
template<int BM,int BN,int BK,int TM,int TN,int EPI>
__global__ void __launch_bounds__((BM/TM)*(BN/TN))
sgemm_nn(int M,int N,int K,
         const float* __restrict__ A,int lda,
         const float* __restrict__ B,int ldb,
         float* __restrict__ C,int ldc,
         const float* __restrict__ bias,
         int zdiv, ll sAo, ll sAi, ll sBo, ll sBi, ll sCo, ll sCi, int tri)
{
    constexpr int THREADS = (BM/TM)*(BN/TN);
    __shared__ __align__(16) float As[BK][BM];
    __shared__ __align__(16) float Bs[BK][BN];

    int bz = blockIdx.z;
    int zo = bz / zdiv, zi = bz % zdiv;
    A += (ll)zo*sAo + (ll)zi*sAi;
    B += (ll)zo*sBo + (ll)zi*sBi;
    C += (ll)zo*sCo + (ll)zi*sCi;

    int bm = blockIdx.y * BM, bn = blockIdx.x * BN;
    int Keff = tri ? min(K, bm + BM) : K;

    int tid = threadIdx.x;
    int tx = tid % (BN/TN), ty = tid / (BN/TN);

    constexpr int LA = (BM*BK)/(4*THREADS);
    constexpr int LB = (BK*BN)/(4*THREADS);
    constexpr int A_RPP = THREADS/(BK/4);
    constexpr int B_RPP = THREADS/(BN/4);
    int a_c4 = tid % (BK/4), a_r = tid / (BK/4);
    int b_c4 = tid % (BN/4), b_r = tid / (BN/4);

    float acc[TM][TN] = {};

    for (int k0 = 0; k0 < Keff; k0 += BK) {
        #pragma unroll
        for (int p = 0; p < LA; p++) {
            int r = a_r + p * A_RPP;
            float4 v = *(const float4*)&A[(ll)(bm + r)*lda + k0 + a_c4*4];
            As[a_c4*4+0][r] = v.x; As[a_c4*4+1][r] = v.y;
            As[a_c4*4+2][r] = v.z; As[a_c4*4+3][r] = v.w;
        }
        #pragma unroll
        for (int p = 0; p < LB; p++) {
            int r = b_r + p * B_RPP;
            *(float4*)&Bs[r][b_c4*4] = *(const float4*)&B[(ll)(k0 + r)*ldb + bn + b_c4*4];
        }
        __syncthreads();
        #pragma unroll
        for (int kk = 0; kk < BK; kk++) {
            float a[TM], b[TN];
            #pragma unroll
            for (int i = 0; i < TM; i += 4)
                *(float4*)&a[i] = *(const float4*)&As[kk][ty*TM + i];
            #pragma unroll
            for (int j = 0; j < TN; j += 4)
                *(float4*)&b[j] = *(const float4*)&Bs[kk][tx*TN + j];
            #pragma unroll
            for (int i = 0; i < TM; i++)
                #pragma unroll
                for (int j = 0; j < TN; j++)
                    acc[i][j] = fmaf(a[i], b[j], acc[i][j]);
        }
        __syncthreads();
    }

    #pragma unroll
    for (int i = 0; i < TM; i++) {
        int row = bm + ty*TM + i;
        float* crow = C + (ll)row*ldc + bn + tx*TN;
        #pragma unroll
        for (int j0 = 0; j0 < TN; j0 += 4) {
            float4 v;
            v.x = acc[i][j0+0]; v.y = acc[i][j0+1];
            v.z = acc[i][j0+2]; v.w = acc[i][j0+3];
            if (EPI >= 1) {
                float4 bv = *(const float4*)&bias[bn + tx*TN + j0];
                v.x += bv.x; v.y += bv.y; v.z += bv.z; v.w += bv.w;
            }
            if (EPI == 2) {
                v.x = fmaxf(v.x, 0.f); v.y = fmaxf(v.y, 0.f);
                v.z = fmaxf(v.z, 0.f); v.w = fmaxf(v.w, 0.f);
            }
            *(float4*)&crow[j0] = v;
        }
    }
}

// ---------------- attention: E = exp(scale * Q K^T) masked (NT GEMM) ----------------
// grid (T/128, T/128, B*H), 256 threads
__global__ void __launch_bounds__(256)
attn_scores_kernel(const float* __restrict__ Q, const float* __restrict__ Km,
                   float* __restrict__ E)
{
    int bz = blockIdx.z;
    int b = bz >> 4, h = bz & 15;
    const float* Qb = Q + (ll)b*Tt*Dd + h*HS;
    const float* Kb = Km + (ll)b*Tt*Dd + h*HS;
    float* Eb = E + (ll)bz*Tt*Tt;

    int bm = blockIdx.y * 128, bn = blockIdx.x * 128;
    int tid = threadIdx.x;

    if (bn > bm + 127) {  // entire tile above diagonal -> zeros
        for (int i = tid; i < 128*32; i += 256) {
            int r = i >> 5, c4 = i & 31;
            *(float4*)&Eb[(ll)(bm + r)*Tt + bn + c4*4] = make_float4(0.f,0.f,0.f,0.f);
        }
        return;
    }

    __shared__ __align__(16) float As[16][128];
    __shared__ __align__(16) float Bs[16][128];
    int tx = tid & 15, ty = tid >> 4;
    int c4 = tid & 3, rr = tid >> 2;   // 64 rows per pass, 4 cols(f4)
    float acc[8][8] = {};

    for (int k0 = 0; k0 < HS; k0 += 16) {
        #pragma unroll
        for (int p = 0; p < 2; p++) {
            int r = rr + p*64;
            float4 v = *(const float4*)&Qb[(ll)(bm + r)*Dd + k0 + c4*4];
            As[c4*4+0][r] = v.x; As[c4*4+1][r] = v.y; As[c4*4+2][r] = v.z; As[c4*4+3][r] = v.w;
            float4 w = *(const float4*)&Kb[(ll)(bn + r)*Dd + k0 + c4*4];
            Bs[c4*4+0][r] = w.x; Bs[c4*4+1][r] = w.y; Bs[c4*4+2][r] = w.z; Bs[c4*4+3][r] = w.w;
        }
        __syncthreads();
        #pragma unroll
        for (int kk = 0; kk < 16; kk++) {
            float a[8], b2[8];
            #pragma unroll
            for (int i = 0; i < 8; i += 4) *(float4*)&a[i]  = *(const float4*)&As[kk][ty*8 + i];
            #pragma unroll
            for (int j = 0; j < 8; j += 4) *(float4*)&b2[j] = *(const float4*)&Bs[kk][tx*8 + j];
            #pragma unroll
            for (int i = 0; i < 8; i++)
                #pragma unroll
                for (int j = 0; j < 8; j++)
                    acc[i][j] = fmaf(a[i], b2[j], acc[i][j]);
        }
        __syncthreads();
    }

    const float scale = 0.03125f;   // D^-0.5 = 1/32
    #pragma unroll
    for (int i = 0; i < 8; i++) {
        int row = bm + ty*8 + i;
        #pragma unroll
        for (int j0 = 0; j0 < 8; j0 += 4) {
            float4 v;
            int col = bn + tx*8 + j0;
            v.x = (col+0 <= row) ? __expf(scale*acc[i][j0+0]) : 0.f;
            v.y = (col+1 <= row) ? __expf(scale*acc[i][j0+1]) : 0.f;
            v.z = (col+2 <= row) ? __expf(scale*acc[i][j0+2]) : 0.f;
            v.w = (col+3 <= row) ? __expf(scale*acc[i][j0+3]) : 0.f;
            *(float4*)&Eb[(ll)row*Tt + col] = v;
        }
    }
}

// ---------------- column-sum inverse over query axis ----------------
__global__ void colinv_kernel(const float* __restrict__ E, float* __restrict__ ci)
{
    int bz = blockIdx.y;
    int s = blockIdx.x * 256 + threadIdx.x;
    const float* Eb = E + (ll)bz*Tt*Tt;
    int t0 = blockIdx.x * 256;  // rows below block start are all zero
    float sum = 0.f;
    for (int t = t0; t < Tt; t++) sum += Eb[(ll)t*Tt + s];
    ci[bz*Tt + s] = 1.f / sum;
}

// ---------------- v' = v / colsum ----------------
__global__ void vscale_kernel(const float* __restrict__ v2, const float* __restrict__ ci,
                              float* __restrict__ vs)
{
    ll i4 = (ll)blockIdx.x * 256 + threadIdx.x;
    ll i = i4 * 4;
    int bt = (int)(i >> 10);
    int d  = (int)(i & 1023);
    int h = d >> 6;
    int b = bt >> 11, t = bt & 2047;
    float c = ci[((b*Hh + h) << 11) + t];
    float4 v = ((const float4*)v2)[i4];
    v.x *= c; v.y *= c; v.z *= c; v.w *= c;
    ((float4*)vs)[i4] = v;
}

// ---------------- layernorm (one block per row, D=1024, 256 threads) ----------------
__global__ void ln_kernel(const float* __restrict__ x, const float* __restrict__ g,
                          const float* __restrict__ bta, float* __restrict__ y)
{
    int row = blockIdx.x, tid = threadIdx.x;
    float4 v = ((const float4*)(x + (ll)row*Dd))[tid];
    float mean = blockReduceSum(v.x + v.y + v.z + v.w) * (1.f/1024.f);
    float dx = v.x - mean, dy = v.y - mean, dz = v.z - mean, dw = v.w - mean;
    float var = blockReduceSum(dx*dx + dy*dy + dz*dz + dw*dw) * (1.f/1024.f);
    float rstd = rsqrtf(var + 1e-5f);
    float4 gv = ((const float4*)g)[tid];
    float4 bv = ((const float4*)bta)[tid];
    float4 o;
    o.x = dx*rstd*gv.x + bv.x; o.y = dy*rstd*gv.y + bv.y;
    o.z = dz*rstd*gv.z + bv.z; o.w = dw*rstd*gv.w + bv.w;
    ((float4*)(y + (ll)row*Dd))[tid] = o;
}

// ---------------- embedding ----------------
__global__ void embed_kernel(const int* __restrict__ idx, const float* __restrict__ tok,
                             const float* __restrict__ pos, float* __restrict__ x)
{
    int bt = blockIdx.x, tid = threadIdx.x;
    int t = bt & (Tt - 1);
    int token = idx[bt];
    float4 a = ((const float4*)(tok + (ll)token*Dd))[tid];
    float4 p = ((const float4*)(pos + (ll)t*Dd))[tid];
    float4 o = make_float4(a.x+p.x, a.y+p.y, a.z+p.z, a.w+p.w);
    ((float4*)(x + (ll)bt*Dd))[tid] = o;
}

// ---------------- elementwise add ----------------
__global__ void add_kernel(const float* __restrict__ a, const float* __restrict__ b,
                           float* __restrict__ c)
{
    ll i = (ll)blockIdx.x * 256 + threadIdx.x;
    float4 av = ((const float4*)a)[i];
    float4 bv = ((const float4*)b)[i];
    ((float4*)c)[i] = make_float4(av.x+bv.x, av.y+bv.y, av.z+bv.z, av.w+bv.w);
}

// ---------------- pack [H,D,hs] -> [D, H*hs] for q/k/v ----------------
__global__ void pack_qkv_kernel(const float* __restrict__ wq, const float* __restrict__ wk,
                                const float* __restrict__ wv,
                                float* __restrict__ pq, float* __restrict__ pk,
                                float* __restrict__ pv)
{
    int n = blockIdx.x * 256 + threadIdx.x;  // over D*D
    int d = n >> 10, c = n & 1023;
    int h = c >> 6, e = c & 63;
    ll src = ((ll)h*Dd + d)*64 + e;
    pq[n] = wq[src]; pk[n] = wk[src]; pv[n] = wv[src];
}

// ---------------- per-row cross-entropy ----------------
__global__ void rowloss_kernel(const float* __restrict__ logits, const int* __restrict__ tg,
                               float* __restrict__ rl)
{
    int row = blockIdx.x, tid = threadIdx.x;
    const float* lr = logits + (ll)row * Vv;
    float mx = -FLT_MAX;
    for (int i = tid; i < Vv; i += 256) mx = fmaxf(mx, lr[i]);
    mx = blockReduceMax(mx);
    float se = 0.f;
    for (int i = tid; i < Vv; i += 256) se += __expf(lr[i] - mx);
    se = blockReduceSum(se);
    if (tid == 0) rl[row] = mx + logf(se) - lr[tg[row]];
}

__global__ void lossreduce_kernel(const float* __restrict__ rl, float* __restrict__ out)
{
    float s = 0.f;
    for (int i = threadIdx.x; i < BT; i += 256) s += rl[i];
    s = blockReduceSum(s);
    if (threadIdx.x == 0) out[0] = s * (1.f / (float)BT);
}

// ---------------- host-side GEMM dispatch ----------------
static void gemm_main(int M, int N, int K, const float* A, int lda,
                      const float* B, int ldb, float* C, int ldc,
                      const float* bias, int epi)
{
    dim3 grid(N/128, M/128, 1);
    if (epi == 0)
        sgemm_nn<128,128,16,8,8,0><<<grid,256>>>(M,N,K,A,lda,B,ldb,C,ldc,bias,1,0,0,0,0,0,0,0);
    else if (epi == 1)
        sgemm_nn<128,128,16,8,8,1><<<grid,256>>>(M,N,K,A,lda,B,ldb,C,ldc,bias,1,0,0,0,0,0,0,0);
    else
        sgemm_nn<128,128,16,8,8,2><<<grid,256>>>(M,N,K,A,lda,B,ldb,C,ldc,bias,1,0,0,0,0,0,0,0);
}

extern "C" void kernel_launch(void* const* d_in, const int* in_sizes, int n_in,
                              void* d_out, int out_size)
{
    const int*   idx   = (const int*)  d_in[0];
    const int*   tgt   = (const int*)  d_in[1];
    const float* tok   = (const float*)d_in[2];
    const float* pos   = (const float*)d_in[3];
    const float* wq    = (const float*)d_in[4];
    const float* wk    = (const float*)d_in[5];
    const float* wv    = (const float*)d_in[6];
    const float* wproj = (const float*)d_in[7];
    const float* bproj = (const float*)d_in[8];
    const float* ln1g  = (const float*)d_in[9];
    const float* ln1b  = (const float*)d_in[10];
    const float* ln2g  = (const float*)d_in[11];
    const float* ln2b  = (const float*)d_in[12];
    const float* w1    = (const float*)d_in[13];
    const float* b1    = (const float*)d_in[14];
    const float* w2    = (const float*)d_in[15];
    const float* b2    = (const float*)d_in[16];
    const float* lnfg  = (const float*)d_in[17];
    const float* lnfb  = (const float*)d_in[18];
    const float* wlm   = (const float*)d_in[19];
    const float* blm   = (const float*)d_in[20];

    float *px,*ph,*pq,*pk,*pv,*pvs,*po,*pp,*pf,*pe,*pci,*pwq,*pwk,*pwv,*prl,*plo;
    cudaGetSymbolAddress((void**)&px,  g_x);
    cudaGetSymbolAddress((void**)&ph,  g_h);
    cudaGetSymbolAddress((void**)&pq,  g_q);
    cudaGetSymbolAddress((void**)&pk,  g_k);
    cudaGetSymbolAddress((void**)&pv,  g_v);
    cudaGetSymbolAddress((void**)&pvs, g_vs);
    cudaGetSymbolAddress((void**)&po,  g_o);
    cudaGetSymbolAddress((void**)&pp,  g_p);
    cudaGetSymbolAddress((void**)&pf,  g_f);
    cudaGetSymbolAddress((void**)&pe,  g_att);
    cudaGetSymbolAddress((void**)&pci, g_ci);
    cudaGetSymbolAddress((void**)&pwq, g_wq);
    cudaGetSymbolAddress((void**)&pwk, g_wk);
    cudaGetSymbolAddress((void**)&pwv, g_wv);
    cudaGetSymbolAddress((void**)&prl, g_rl);
    cudaGetSymbolAddress((void**)&plo, g_loss);

    float* out = (float*)d_out;
    const ll NL = (ll)BT * Vv;               // 131,072,000
    float* logits = (out_size >= (int)NL) ? out : pe;   // reuse E scratch if needed
    float* lossp  = plo;
    if ((ll)out_size == NL + 1) lossp = out + NL;
    else if (out_size == 1)     lossp = out;

    embed_kernel<<<BT, 256>>>(idx, tok, pos, px);

    for (int l = 0; l < Ll; l++) {
        ln_kernel<<<BT, 256>>>(px, ln1g + (ll)l*Dd, ln1b + (ll)l*Dd, ph);

        pack_qkv_kernel<<<(Dd*Dd)/256, 256>>>(
            wq + (ll)l*Hh*Dd*HS, wk + (ll)l*Hh*Dd*HS, wv + (ll)l*Hh*Dd*HS,
            pwq, pwk, pwv);

        gemm_main(BT, Dd, Dd, ph, Dd, pwq, Dd, pq, Dd, nullptr, 0);
        gemm_main(BT, Dd, Dd, ph, Dd, pwk, Dd, pk, Dd, nullptr, 0);
        gemm_main(BT, Dd, Dd, ph, Dd, pwv, Dd, pv, Dd, nullptr, 0);

        attn_scores_kernel<<<dim3(Tt/128, Tt/128, Bb*Hh), 256>>>(pq, pk, pe);
        colinv_kernel<<<dim3(Tt/256, Bb*Hh), 256>>>(pe, pci);
        vscale_kernel<<<(BT*Dd)/1024, 256>>>(pv, pci, pvs);

        // O = E @ V'   batched over (b,h): M=T, N=64, K=T, causal K truncation
        {
            dim3 grid(1, Tt/128, Bb*Hh);
            sgemm_nn<128,64,16,8,8,0><<<grid,128>>>(
                Tt, 64, Tt,
                pe, Tt,
                pvs, Dd,
                po, Dd,
                nullptr,
                Hh,
                (ll)Hh*Tt*Tt, (ll)Tt*Tt,   // A: bz*T*T
                (ll)Tt*Dd, 64LL,           // B: b*T*D + h*64
                (ll)Tt*Dd, 64LL,           // C: b*T*D + h*64
                1);
        }

        gemm_main(BT, Dd, Dd, po, Dd, wproj + (ll)l*Dd*Dd, Dd, pp, Dd,
                  bproj + (ll)l*Dd, 1);
        add_kernel<<<(BT*Dd)/1024, 256>>>(ph, pp, px);           // x = h + o

        ln_kernel<<<BT, 256>>>(px, ln2g + (ll)l*Dd, ln2b + (ll)l*Dd, ph);
        gemm_main(BT, Ff, Dd, ph, Dd, w1 + (ll)l*Dd*Ff, Ff, pf, Ff,
                  b1 + (ll)l*Ff, 2);                             // relu
        gemm_main(BT, Dd, Ff, pf, Ff, w2 + (ll)l*Ff*Dd, Dd, pp, Dd,
                  b2 + (ll)l*Dd, 1);
        add_kernel<<<(BT*Dd)/1024, 256>>>(ph, pp, px);           // x = h2 + f
    }

    ln_kernel<<<BT, 256>>>(px, lnfg, lnfb, ph);
    gemm_main(BT, Vv, Dd, ph, Dd, wlm, Vv, logits, Vv, blm, 1);

    rowloss_kernel<<<BT, 256>>>(logits, tgt, prl);
    lossreduce_kernel<<<1, 256>>>(prl, lossp);
}

// round 17
// speedup vs baseline: 1.0304x; 1.0282x over previous
#include <cuda_runtime.h>
#include <math.h>
#include <float.h>

typedef long long ll;

#define Bb 2
#define Tt 2048
#define BT 4096
#define Dd 1024
#define Hh 16
#define HS 64
#define Ff 4096
#define Vv 32000
#define Ll 8

// ---------------- static scratch (no allocations allowed) ----------------
__device__ float g_x [BT*Dd];
__device__ float g_h [BT*Dd];
__device__ float g_q [BT*Dd];
__device__ float g_k [BT*Dd];
__device__ float g_v [BT*Dd];
__device__ float g_vs[BT*Dd];
__device__ float g_o [BT*Dd];
__device__ float g_p [BT*Dd];
__device__ float g_f [BT*Ff];
__device__ float g_att[134217728];     // B*H*T*T = 512MB
__device__ float g_ci [Bb*Hh*Tt];
__device__ float g_wq [Dd*Dd];
__device__ float g_wk [Dd*Dd];
__device__ float g_wv [Dd*Dd];
__device__ float g_rl [BT];
__device__ float g_loss[4];

// ---------------- cp.async helpers ----------------
__device__ __forceinline__ void cp_async16(void* smem, const void* gmem){
    unsigned saddr = (unsigned)__cvta_generic_to_shared(smem);
    asm volatile("cp.async.cg.shared.global [%0], [%1], 16;\n" :: "r"(saddr), "l"(gmem));
}
__device__ __forceinline__ void cp_async_commit(){ asm volatile("cp.async.commit_group;\n" ::: "memory"); }
__device__ __forceinline__ void cp_async_wait0(){ asm volatile("cp.async.wait_group 0;\n" ::: "memory"); }

// ---------------- reductions ----------------
__device__ __forceinline__ float blockReduceSum(float v){
    __shared__ float sh[33];
    int lane = threadIdx.x & 31, wid = threadIdx.x >> 5;
    #pragma unroll
    for (int o = 16; o; o >>= 1) v += __shfl_xor_sync(0xffffffffu, v, o);
    __syncthreads();
    if (lane == 0) sh[wid] = v;
    __syncthreads();
    if (wid == 0) {
        int nw = (blockDim.x + 31) >> 5;
        float r = (lane < nw) ? sh[lane] : 0.f;
        #pragma unroll
        for (int o = 16; o; o >>= 1) r += __shfl_xor_sync(0xffffffffu, r, o);
        if (lane == 0) sh[32] = r;
    }
    __syncthreads();
    return sh[32];
}

__device__ __forceinline__ float blockReduceMax(float v){
    __shared__ float shm[33];
    int lane = threadIdx.x & 31, wid = threadIdx.x >> 5;
    #pragma unroll
    for (int o = 16; o; o >>= 1) v = fmaxf(v, __shfl_xor_sync(0xffffffffu, v, o));
    __syncthreads();
    if (lane == 0) shm[wid] = v;
    __syncthreads();
    if (wid == 0) {
        int nw = (blockDim.x + 31) >> 5;
        float r = (lane < nw) ? shm[lane] : -FLT_MAX;
        #pragma unroll
        for (int o = 16; o; o >>= 1) r = fmaxf(r, __shfl_xor_sync(0xffffffffu, r, o));
        if (lane == 0) shm[32] = r;
    }
    __syncthreads();
    return shm[32];
}

// ---------------- double-buffered SGEMM (NN) with fused epilogue ----------------
// C[M,N] = A[M,K] * B[K,N]; EPI: 0=none, 1=+bias, 2=relu(+bias)
// batch offset: bz -> zo=bz/zdiv, zi=bz%zdiv ; base += zo*sXo + zi*sXi
// tri!=0: K truncated to bm+BM (causal lower-triangular A)
template<int BM,int BN,int BK,int TM,int TN,int EPI>
__global__ void __launch_bounds__((BM/TM)*(BN/TN), 512/((BM/TM)*(BN/TN)))
sgemm_nn(int M,int N,int K,
         const float* __restrict__ A,int lda,
         const float* __restrict__ B,int ldb,
         float* __restrict__ C,int ldc,
         const float* __restrict__ bias,
         int zdiv, ll sAo, ll sAi, ll sBo, ll sBi, ll sCo, ll sCi, int tri)
{
    constexpr int THREADS = (BM/TM)*(BN/TN);
    __shared__ __align__(16) float As[2][BK][BM];
    __shared__ __align__(16) float Bs[2][BK][BN];

    int bz = blockIdx.z;
    int zo = bz / zdiv, zi = bz % zdiv;
    A += (ll)zo*sAo + (ll)zi*sAi;
    B += (ll)zo*sBo + (ll)zi*sBi;
    C += (ll)zo*sCo + (ll)zi*sCi;

    int bm = blockIdx.y * BM, bn = blockIdx.x * BN;
    int Keff = tri ? min(K, bm + BM) : K;
    int nt = Keff / BK;

    int tid = threadIdx.x;
    int tx = tid % (BN/TN), ty = tid / (BN/TN);

    constexpr int LA = (BM*BK)/(4*THREADS);
    constexpr int LB = (BK*BN)/(4*THREADS);
    constexpr int A_RPP = THREADS/(BK/4);
    constexpr int B_RPP = THREADS/(BN/4);
    int a_c4 = tid % (BK/4), a_r = tid / (BK/4);
    int b_c4 = tid % (BN/4), b_r = tid / (BN/4);

    // ---- prologue: stage 0 ----
    {
        #pragma unroll
        for (int p = 0; p < LA; p++) {
            int r = a_r + p * A_RPP;
            float4 v = *(const float4*)&A[(ll)(bm + r)*lda + a_c4*4];
            As[0][a_c4*4+0][r] = v.x; As[0][a_c4*4+1][r] = v.y;
            As[0][a_c4*4+2][r] = v.z; As[0][a_c4*4+3][r] = v.w;
        }
        #pragma unroll
        for (int p = 0; p < LB; p++) {
            int r = b_r + p * B_RPP;
            cp_async16(&Bs[0][r][b_c4*4], &B[(ll)r*ldb + bn + b_c4*4]);
        }
        cp_async_commit();
    }
    cp_async_wait0();
    __syncthreads();

    float acc[TM][TN] = {};
    int cur = 0;

    for (int i = 0; i < nt; i++) {
        float4 Areg[LA];
        bool more = (i + 1 < nt);
        int k0n = (i + 1) * BK;
        if (more) {
            #pragma unroll
            for (int p = 0; p < LA; p++) {
                int r = a_r + p * A_RPP;
                Areg[p] = *(const float4*)&A[(ll)(bm + r)*lda + k0n + a_c4*4];
            }
            #pragma unroll
            for (int p = 0; p < LB; p++) {
                int r = b_r + p * B_RPP;
                cp_async16(&Bs[cur^1][r][b_c4*4], &B[(ll)(k0n + r)*ldb + bn + b_c4*4]);
            }
            cp_async_commit();
        }

        #pragma unroll
        for (int kk = 0; kk < BK; kk++) {
            float a[TM], b[TN];
            #pragma unroll
            for (int ii = 0; ii < TM; ii += 4)
                *(float4*)&a[ii] = *(const float4*)&As[cur][kk][ty*TM + ii];
            #pragma unroll
            for (int jj = 0; jj < TN; jj += 4)
                *(float4*)&b[jj] = *(const float4*)&Bs[cur][kk][tx*TN + jj];
            #pragma unroll
            for (int ii = 0; ii < TM; ii++)
                #pragma unroll
                for (int jj = 0; jj < TN; jj++)
                    acc[ii][jj] = fmaf(a[ii], b[jj], acc[ii][jj]);
        }

        if (more) {
            #pragma unroll
            for (int p = 0; p < LA; p++) {
                int r = a_r + p * A_RPP;
                As[cur^1][a_c4*4+0][r] = Areg[p].x;
                As[cur^1][a_c4*4+1][r] = Areg[p].y;
                As[cur^1][a_c4*4+2][r] = Areg[p].z;
                As[cur^1][a_c4*4+3][r] = Areg[p].w;
            }
            cp_async_wait0();
        }
        __syncthreads();
        cur ^= 1;
    }

    #pragma unroll
    for (int i = 0; i < TM; i++) {
        int row = bm + ty*TM + i;
        float* crow = C + (ll)row*ldc + bn + tx*TN;
        #pragma unroll
        for (int j0 = 0; j0 < TN; j0 += 4) {
            float4 v;
            v.x = acc[i][j0+0]; v.y = acc[i][j0+1];
            v.z = acc[i][j0+2]; v.w = acc[i][j0+3];
            if (EPI >= 1) {
                float4 bv = *(const float4*)&bias[bn + tx*TN + j0];
                v.x += bv.x; v.y += bv.y; v.z += bv.z; v.w += bv.w;
            }
            if (EPI == 2) {
                v.x = fmaxf(v.x, 0.f); v.y = fmaxf(v.y, 0.f);
                v.z = fmaxf(v.z, 0.f); v.w = fmaxf(v.w, 0.f);
            }
            *(float4*)&crow[j0] = v;
        }
    }
}

// ---------------- attention: E = exp(scale * Q K^T) masked (NT GEMM) ----------------
// grid (T/128, T/128, B*H), 256 threads
__global__ void __launch_bounds__(256)
attn_scores_kernel(const float* __restrict__ Q, const float* __restrict__ Km,
                   float* __restrict__ E)
{
    int bz = blockIdx.z;
    int b = bz >> 4, h = bz & 15;
    const float* Qb = Q + (ll)b*Tt*Dd + h*HS;
    const float* Kb = Km + (ll)b*Tt*Dd + h*HS;
    float* Eb = E + (ll)bz*Tt*Tt;

    int bm = blockIdx.y * 128, bn = blockIdx.x * 128;
    int tid = threadIdx.x;

    if (bn > bm + 127) {  // entire tile above diagonal -> zeros
        for (int i = tid; i < 128*32; i += 256) {
            int r = i >> 5, c4 = i & 31;
            *(float4*)&Eb[(ll)(bm + r)*Tt + bn + c4*4] = make_float4(0.f,0.f,0.f,0.f);
        }
        return;
    }

    __shared__ __align__(16) float As[16][128];
    __shared__ __align__(16) float Bs[16][128];
    int tx = tid & 15, ty = tid >> 4;
    int c4 = tid & 3, rr = tid >> 2;   // 64 rows per pass, 4 cols(f4)
    float acc[8][8] = {};

    for (int k0 = 0; k0 < HS; k0 += 16) {
        #pragma unroll
        for (int p = 0; p < 2; p++) {
            int r = rr + p*64;
            float4 v = *(const float4*)&Qb[(ll)(bm + r)*Dd + k0 + c4*4];
            As[c4*4+0][r] = v.x; As[c4*4+1][r] = v.y; As[c4*4+2][r] = v.z; As[c4*4+3][r] = v.w;
            float4 w = *(const float4*)&Kb[(ll)(bn + r)*Dd + k0 + c4*4];
            Bs[c4*4+0][r] = w.x; Bs[c4*4+1][r] = w.y; Bs[c4*4+2][r] = w.z; Bs[c4*4+3][r] = w.w;
        }
        __syncthreads();
        #pragma unroll
        for (int kk = 0; kk < 16; kk++) {
            float a[8], b2[8];
            #pragma unroll
            for (int i = 0; i < 8; i += 4) *(float4*)&a[i]  = *(const float4*)&As[kk][ty*8 + i];
            #pragma unroll
            for (int j = 0; j < 8; j += 4) *(float4*)&b2[j] = *(const float4*)&Bs[kk][tx*8 + j];
            #pragma unroll
            for (int i = 0; i < 8; i++)
                #pragma unroll
                for (int j = 0; j < 8; j++)
                    acc[i][j] = fmaf(a[i], b2[j], acc[i][j]);
        }
        __syncthreads();
    }

    const float scale = 0.03125f;   // D^-0.5 = 1/32
    #pragma unroll
    for (int i = 0; i < 8; i++) {
        int row = bm + ty*8 + i;
        #pragma unroll
        for (int j0 = 0; j0 < 8; j0 += 4) {
            float4 v;
            int col = bn + tx*8 + j0;
            v.x = (col+0 <= row) ? __expf(scale*acc[i][j0+0]) : 0.f;
            v.y = (col+1 <= row) ? __expf(scale*acc[i][j0+1]) : 0.f;
            v.z = (col+2 <= row) ? __expf(scale*acc[i][j0+2]) : 0.f;
            v.w = (col+3 <= row) ? __expf(scale*acc[i][j0+3]) : 0.f;
            *(float4*)&Eb[(ll)row*Tt + col] = v;
        }
    }
}

// ---------------- column-sum inverse over query axis ----------------
__global__ void colinv_kernel(const float* __restrict__ E, float* __restrict__ ci)
{
    int bz = blockIdx.y;
    int s = blockIdx.x * 256 + threadIdx.x;
    const float* Eb = E + (ll)bz*Tt*Tt;
    int t0 = blockIdx.x * 256;  // rows below block start are all zero
    float sum = 0.f;
    for (int t = t0; t < Tt; t++) sum += Eb[(ll)t*Tt + s];
    ci[bz*Tt + s] = 1.f / sum;
}

// ---------------- v' = v / colsum ----------------
__global__ void vscale_kernel(const float* __restrict__ v2, const float* __restrict__ ci,
                              float* __restrict__ vs)
{
    ll i4 = (ll)blockIdx.x * 256 + threadIdx.x;
    ll i = i4 * 4;
    int bt = (int)(i >> 10);
    int d  = (int)(i & 1023);
    int h = d >> 6;
    int b = bt >> 11, t = bt & 2047;
    float c = ci[((b*Hh + h) << 11) + t];
    float4 v = ((const float4*)v2)[i4];
    v.x *= c; v.y *= c; v.z *= c; v.w *= c;
    ((float4*)vs)[i4] = v;
}

// ---------------- layernorm (one block per row, D=1024, 256 threads) ----------------
__global__ void ln_kernel(const float* __restrict__ x, const float* __restrict__ g,
                          const float* __restrict__ bta, float* __restrict__ y)
{
    int row = blockIdx.x, tid = threadIdx.x;
    float4 v = ((const float4*)(x + (ll)row*Dd))[tid];
    float mean = blockReduceSum(v.x + v.y + v.z + v.w) * (1.f/1024.f);
    float dx = v.x - mean, dy = v.y - mean, dz = v.z - mean, dw = v.w - mean;
    float var = blockReduceSum(dx*dx + dy*dy + dz*dz + dw*dw) * (1.f/1024.f);
    float rstd = rsqrtf(var + 1e-5f);
    float4 gv = ((const float4*)g)[tid];
    float4 bv = ((const float4*)bta)[tid];
    float4 o;
    o.x = dx*rstd*gv.x + bv.x; o.y = dy*rstd*gv.y + bv.y;
    o.z = dz*rstd*gv.z + bv.z; o.w = dw*rstd*gv.w + bv.w;
    ((float4*)(y + (ll)row*Dd))[tid] = o;
}

// ---------------- embedding ----------------
__global__ void embed_kernel(const int* __restrict__ idx, const float* __restrict__ tok,
                             const float* __restrict__ pos, float* __restrict__ x)
{
    int bt = blockIdx.x, tid = threadIdx.x;
    int t = bt & (Tt - 1);
    int token = idx[bt];
    float4 a = ((const float4*)(tok + (ll)token*Dd))[tid];
    float4 p = ((const float4*)(pos + (ll)t*Dd))[tid];
    float4 o = make_float4(a.x+p.x, a.y+p.y, a.z+p.z, a.w+p.w);
    ((float4*)(x + (ll)bt*Dd))[tid] = o;
}

// ---------------- elementwise add ----------------
__global__ void add_kernel(const float* __restrict__ a, const float* __restrict__ b,
                           float* __restrict__ c)
{
    ll i = (ll)blockIdx.x * 256 + threadIdx.x;
    float4 av = ((const float4*)a)[i];
    float4 bv = ((const float4*)b)[i];
    ((float4*)c)[i] = make_float4(av.x+bv.x, av.y+bv.y, av.z+bv.z, av.w+bv.w);
}

// ---------------- pack [H,D,hs] -> [D, H*hs] for q/k/v ----------------
__global__ void pack_qkv_kernel(const float* __restrict__ wq, const float* __restrict__ wk,
                                const float* __restrict__ wv,
                                float* __restrict__ pq, float* __restrict__ pk,
                                float* __restrict__ pv)
{
    int n = blockIdx.x * 256 + threadIdx.x;  // over D*D
    int d = n >> 10, c = n & 1023;
    int h = c >> 6, e = c & 63;
    ll src = ((ll)h*Dd + d)*64 + e;
    pq[n] = wq[src]; pk[n] = wk[src]; pv[n] = wv[src];
}

// ---------------- per-row cross-entropy ----------------
__global__ void rowloss_kernel(const float* __restrict__ logits, const int* __restrict__ tg,
                               float* __restrict__ rl)
{
    int row = blockIdx.x, tid = threadIdx.x;
    const float* lr = logits + (ll)row * Vv;
    float mx = -FLT_MAX;
    for (int i = tid; i < Vv; i += 256) mx = fmaxf(mx, lr[i]);
    mx = blockReduceMax(mx);
    float se = 0.f;
    for (int i = tid; i < Vv; i += 256) se += __expf(lr[i] - mx);
    se = blockReduceSum(se);
    if (tid == 0) rl[row] = mx + logf(se) - lr[tg[row]];
}

__global__ void lossreduce_kernel(const float* __restrict__ rl, float* __restrict__ out)
{
    float s = 0.f;
    for (int i = threadIdx.x; i < BT; i += 256) s += rl[i];
    s = blockReduceSum(s);
    if (threadIdx.x == 0) out[0] = s * (1.f / (float)BT);
}

// ---------------- host-side GEMM dispatch ----------------
static void gemm_main(int M, int N, int K, const float* A, int lda,
                      const float* B, int ldb, float* C, int ldc,
                      const float* bias, int epi)
{
    dim3 grid(N/128, M/128, 1);
    if (epi == 0)
        sgemm_nn<128,128,16,8,8,0><<<grid,256>>>(M,N,K,A,lda,B,ldb,C,ldc,bias,1,0,0,0,0,0,0,0);
    else if (epi == 1)
        sgemm_nn<128,128,16,8,8,1><<<grid,256>>>(M,N,K,A,lda,B,ldb,C,ldc,bias,1,0,0,0,0,0,0,0);
    else
        sgemm_nn<128,128,16,8,8,2><<<grid,256>>>(M,N,K,A,lda,B,ldb,C,ldc,bias,1,0,0,0,0,0,0,0);
}

extern "C" void kernel_launch(void* const* d_in, const int* in_sizes, int n_in,
                              void* d_out, int out_size)
{
    const int*   idx   = (const int*)  d_in[0];
    const int*   tgt   = (const int*)  d_in[1];
    const float* tok   = (const float*)d_in[2];
    const float* pos   = (const float*)d_in[3];
    const float* wq    = (const float*)d_in[4];
    const float* wk    = (const float*)d_in[5];
    const float* wv    = (const float*)d_in[6];
    const float* wproj = (const float*)d_in[7];
    const float* bproj = (const float*)d_in[8];
    const float* ln1g  = (const float*)d_in[9];
    const float* ln1b  = (const float*)d_in[10];
    const float* ln2g  = (const float*)d_in[11];
    const float* ln2b  = (const float*)d_in[12];
    const float* w1    = (const float*)d_in[13];
    const float* b1    = (const float*)d_in[14];
    const float* w2    = (const float*)d_in[15];
    const float* b2    = (const float*)d_in[16];
    const float* lnfg  = (const float*)d_in[17];
    const float* lnfb  = (const float*)d_in[18];
    const float* wlm   = (const float*)d_in[19];
    const float* blm   = (const float*)d_in[20];

    float *px,*ph,*pq,*pk,*pv,*pvs,*po,*pp,*pf,*pe,*pci,*pwq,*pwk,*pwv,*prl,*plo;
    cudaGetSymbolAddress((void**)&px,  g_x);
    cudaGetSymbolAddress((void**)&ph,  g_h);
    cudaGetSymbolAddress((void**)&pq,  g_q);
    cudaGetSymbolAddress((void**)&pk,  g_k);
    cudaGetSymbolAddress((void**)&pv,  g_v);
    cudaGetSymbolAddress((void**)&pvs, g_vs);
    cudaGetSymbolAddress((void**)&po,  g_o);
    cudaGetSymbolAddress((void**)&pp,  g_p);
    cudaGetSymbolAddress((void**)&pf,  g_f);
    cudaGetSymbolAddress((void**)&pe,  g_att);
    cudaGetSymbolAddress((void**)&pci, g_ci);
    cudaGetSymbolAddress((void**)&pwq, g_wq);
    cudaGetSymbolAddress((void**)&pwk, g_wk);
    cudaGetSymbolAddress((void**)&pwv, g_wv);
    cudaGetSymbolAddress((void**)&prl, g_rl);
    cudaGetSymbolAddress((void**)&plo, g_loss);

    float* out = (float*)d_out;
    const ll NL = (ll)BT * Vv;               // 131,072,000
    float* logits = (out_size >= (int)NL) ? out : pe;   // reuse E scratch if needed
    float* lossp  = plo;
    if ((ll)out_size == NL + 1) lossp = out + NL;
    else if (out_size == 1)     lossp = out;

    embed_kernel<<<BT, 256>>>(idx, tok, pos, px);

    for (int l = 0; l < Ll; l++) {
        ln_kernel<<<BT, 256>>>(px, ln1g + (ll)l*Dd, ln1b + (ll)l*Dd, ph);

        pack_qkv_kernel<<<(Dd*Dd)/256, 256>>>(
            wq + (ll)l*Hh*Dd*HS, wk + (ll)l*Hh*Dd*HS, wv + (ll)l*Hh*Dd*HS,
            pwq, pwk, pwv);

        gemm_main(BT, Dd, Dd, ph, Dd, pwq, Dd, pq, Dd, nullptr, 0);
        gemm_main(BT, Dd, Dd, ph, Dd, pwk, Dd, pk, Dd, nullptr, 0);
        gemm_main(BT, Dd, Dd, ph, Dd, pwv, Dd, pv, Dd, nullptr, 0);

        attn_scores_kernel<<<dim3(Tt/128, Tt/128, Bb*Hh), 256>>>(pq, pk, pe);
        colinv_kernel<<<dim3(Tt/256, Bb*Hh), 256>>>(pe, pci);
        vscale_kernel<<<(BT*Dd)/1024, 256>>>(pv, pci, pvs);

        // O = E @ V'   batched over (b,h): M=T, N=64, K=T, causal K truncation
        {
            dim3 grid(1, Tt/128, Bb*Hh);
            sgemm_nn<128,64,16,8,8,0><<<grid,128>>>(
                Tt, 64, Tt,
                pe, Tt,
                pvs, Dd,
                po, Dd,
                nullptr,
                Hh,
                (ll)Hh*Tt*Tt, (ll)Tt*Tt,   // A: bz*T*T
                (ll)Tt*Dd, 64LL,           // B: b*T*D + h*64
                (ll)Tt*Dd, 64LL,           // C: b*T*D + h*64
                1);
        }

        gemm_main(BT, Dd, Dd, po, Dd, wproj + (ll)l*Dd*Dd, Dd, pp, Dd,
                  bproj + (ll)l*Dd, 1);
        add_kernel<<<(BT*Dd)/1024, 256>>>(ph, pp, px);           // x = h + o

        ln_kernel<<<BT, 256>>>(px, ln2g + (ll)l*Dd, ln2b + (ll)l*Dd, ph);
        gemm_main(BT, Ff, Dd, ph, Dd, w1 + (ll)l*Dd*Ff, Ff, pf, Ff,
                  b1 + (ll)l*Ff, 2);                             // relu
        gemm_main(BT, Dd, Ff, pf, Ff, w2 + (ll)l*Ff*Dd, Dd, pp, Dd,
                  b2 + (ll)l*Dd, 1);
        add_kernel<<<(BT*Dd)/1024, 256>>>(ph, pp, px);           // x = h2 + f
    }

    ln_kernel<<<BT, 256>>>(px, lnfg, lnfb, ph);
    gemm_main(BT, Vv, Dd, ph, Dd, wlm, Vv, logits, Vv, blm, 1);

    rowloss_kernel<<<BT, 256>>>(logits, tgt, prl);
    lossreduce_kernel<<<1, 256>>>(prl, lossp);
}